// round 3
// baseline (speedup 1.0000x reference)
#include <cuda_runtime.h>

// ---------------- problem constants ----------------
#define B_   2
#define T_   1024
#define DM   1024      // d_model
#define DI   2048      // d_inner
#define DS   16        // d_state
#define DC   4         // d_conv
#define TOK  (B_ * T_) // 2048 tokens
#define NCH  16        // scan chunks
#define CHL  64        // chunk length (NCH*CHL == T_)

// ---------------- scratch (static device memory; no allocs allowed) ----------------
__device__ float g_xn  [TOK * DM];            //  8 MB  layernorm output
__device__ float g_proj[TOK * 2 * DI];        // 32 MB  in_proj output (xp | gate)
__device__ float g_xc  [TOK * DI];            // 16 MB  conv+silu output
__device__ float g_Bt  [TOK * DS];            //        B_t
__device__ float g_Ct  [TOK * DS];            //        C_t
__device__ float g_E   [B_ * NCH * DI * DS];  //  4 MB  chunk-local end states
__device__ float g_S   [B_ * NCH * DI * DS];  //  4 MB  chunk initial states (carries)
__device__ float g_y   [TOK * DI];            // 16 MB  gated SSM output

// ---------------- packed f32x2 helpers (Blackwell FFMA2) ----------------
__device__ __forceinline__ unsigned long long fma2(unsigned long long a,
                                                   unsigned long long b,
                                                   unsigned long long c) {
    unsigned long long d;
    asm("fma.rn.f32x2 %0, %1, %2, %3;" : "=l"(d) : "l"(a), "l"(b), "l"(c));
    return d;
}
__device__ __forceinline__ unsigned long long pack2(float x) {
    unsigned long long d;
    asm("mov.b64 %0, {%1, %1};" : "=l"(d) : "f"(x));
    return d;
}
__device__ __forceinline__ float2 unpack2(unsigned long long v) {
    float2 r;
    asm("mov.b64 {%0, %1}, %2;" : "=f"(r.x), "=f"(r.y) : "l"(v));
    return r;
}

__device__ __forceinline__ float sigmoidf_(float x) {
    return 1.0f / (1.0f + __expf(-x));
}
__device__ __forceinline__ float siluf_(float x) {
    return x / (1.0f + __expf(-x));
}

// ---------------- 1. LayerNorm ----------------
__global__ void ln_kernel(const float* __restrict__ x,
                          const float* __restrict__ g,
                          const float* __restrict__ b) {
    int row = blockIdx.x;           // token
    int tid = threadIdx.x;          // 256 threads, 4 elems each
    const float4* xr = (const float4*)(x + (size_t)row * DM);
    float4 v = xr[tid];
    float s = v.x + v.y + v.z + v.w;
    float q = v.x * v.x + v.y * v.y + v.z * v.z + v.w * v.w;
    #pragma unroll
    for (int o = 16; o; o >>= 1) {
        s += __shfl_down_sync(0xFFFFFFFFu, s, o);
        q += __shfl_down_sync(0xFFFFFFFFu, q, o);
    }
    __shared__ float ss[8], sq[8];
    __shared__ float smu, srstd;
    int w = tid >> 5, l = tid & 31;
    if (l == 0) { ss[w] = s; sq[w] = q; }
    __syncthreads();
    if (tid == 0) {
        float S = 0.f, Q = 0.f;
        #pragma unroll
        for (int i = 0; i < 8; i++) { S += ss[i]; Q += sq[i]; }
        float mu = S * (1.0f / DM);
        float var = Q * (1.0f / DM) - mu * mu;
        smu = mu;
        srstd = rsqrtf(var + 1e-5f);
    }
    __syncthreads();
    float mu = smu, rstd = srstd;
    float4 gv = ((const float4*)g)[tid];
    float4 bv = ((const float4*)b)[tid];
    float4 o;
    o.x = (v.x - mu) * rstd * gv.x + bv.x;
    o.y = (v.y - mu) * rstd * gv.y + bv.y;
    o.z = (v.z - mu) * rstd * gv.z + bv.z;
    o.w = (v.w - mu) * rstd * gv.w + bv.w;
    ((float4*)(g_xn + (size_t)row * DM))[tid] = o;
}

// ---------------- 2. / 8. tiled f32x2 GEMM  C = A*B + bias (+ resid) ----------------
// A: MxK row-major, B: KxN row-major, C: MxN. M,N mult of 128; K mult of 16.
template <int EPI>
__global__ __launch_bounds__(256) void gemm_f32x2(
    const float* __restrict__ Amat, const float* __restrict__ Bmat,
    const float* __restrict__ bias, const float* __restrict__ resid,
    float* __restrict__ Cmat, int M, int N, int K)
{
    __shared__ float As[16][132];   // transposed A tile, padded (bank-conflict-free)
    __shared__ float Bs[16][128];
    int tid = threadIdx.x;
    int tx = tid & 15, ty = tid >> 4;
    int mBase = blockIdx.y * 128;
    int nBase = blockIdx.x * 128;

    unsigned long long acc[8][4];
    #pragma unroll
    for (int i = 0; i < 8; i++)
        #pragma unroll
        for (int j = 0; j < 4; j++) acc[i][j] = 0ull;

    for (int k0 = 0; k0 < K; k0 += 16) {
        #pragma unroll
        for (int rep = 0; rep < 2; rep++) {         // A tile: 128x16 (transpose into SMEM)
            int idx = tid + rep * 256;
            int m  = idx >> 2;
            int kq = (idx & 3) << 2;
            float4 v = *(const float4*)(Amat + (size_t)(mBase + m) * K + k0 + kq);
            As[kq + 0][m] = v.x; As[kq + 1][m] = v.y;
            As[kq + 2][m] = v.z; As[kq + 3][m] = v.w;
        }
        #pragma unroll
        for (int rep = 0; rep < 2; rep++) {         // B tile: 16x128
            int idx = tid + rep * 256;
            int r = idx >> 5;
            int c = (idx & 31) << 2;
            *(float4*)&Bs[r][c] = *(const float4*)(Bmat + (size_t)(k0 + r) * N + nBase + c);
        }
        __syncthreads();
        #pragma unroll
        for (int kk = 0; kk < 16; kk++) {
            float4 a0 = *(const float4*)&As[kk][ty * 8];
            float4 a1 = *(const float4*)&As[kk][ty * 8 + 4];
            ulonglong2 b0 = *(const ulonglong2*)&Bs[kk][tx * 8];
            ulonglong2 b1 = *(const ulonglong2*)&Bs[kk][tx * 8 + 4];
            unsigned long long bp0 = b0.x, bp1 = b0.y, bp2 = b1.x, bp3 = b1.y;
            float av[8] = {a0.x, a0.y, a0.z, a0.w, a1.x, a1.y, a1.z, a1.w};
            #pragma unroll
            for (int i = 0; i < 8; i++) {
                unsigned long long ad = pack2(av[i]);
                acc[i][0] = fma2(ad, bp0, acc[i][0]);
                acc[i][1] = fma2(ad, bp1, acc[i][1]);
                acc[i][2] = fma2(ad, bp2, acc[i][2]);
                acc[i][3] = fma2(ad, bp3, acc[i][3]);
            }
        }
        __syncthreads();
    }
    #pragma unroll
    for (int i = 0; i < 8; i++) {
        int m = mBase + ty * 8 + i;
        float* crow = Cmat + (size_t)m * N;
        const float* rrow = resid + (size_t)m * N;  // unused when EPI==0
        #pragma unroll
        for (int j = 0; j < 4; j++) {
            int n = nBase + tx * 8 + j * 2;
            float2 v = unpack2(acc[i][j]);
            v.x += bias[n];
            v.y += bias[n + 1];
            if (EPI) { v.x += rrow[n]; v.y += rrow[n + 1]; }
            *(float2*)(crow + n) = v;
        }
    }
}

// ---------------- 3. depthwise causal conv1d + silu ----------------
__global__ void conv_silu_kernel(const float* __restrict__ cw,
                                 const float* __restrict__ cb) {
    int i = blockIdx.x * 256 + threadIdx.x;   // over TOK*DI
    int d   = i & (DI - 1);
    int tok = i >> 11;                        // DI = 2048
    int t   = tok & (T_ - 1);
    float4 w = *(const float4*)(cw + d * 4);  // conv_w[d,0,0..3]
    const float* base = g_proj + (size_t)tok * (2 * DI) + d;  // xp column d
    float acc = cb[d];
    if (t >= 3) acc = fmaf(w.x, base[-3 * 2 * DI], acc);
    if (t >= 2) acc = fmaf(w.y, base[-2 * 2 * DI], acc);
    if (t >= 1) acc = fmaf(w.z, base[-1 * 2 * DI], acc);
    acc = fmaf(w.w, base[0], acc);
    g_xc[i] = siluf_(acc);
}

// ---------------- 4. B_t / C_t skinny GEMM (N=32) ----------------
__global__ __launch_bounds__(256) void bc_kernel(
    const float* __restrict__ WB, const float* __restrict__ bB,
    const float* __restrict__ WC, const float* __restrict__ bC)
{
    __shared__ float Xs[32][33];
    __shared__ float Ws[32][32];
    int tid = threadIdx.x;
    int tok0 = blockIdx.x * 32;
    int o = tid & 31, tr = tid >> 5;   // output col, token sub-row (per warp)
    float acc[4] = {0.f, 0.f, 0.f, 0.f};
    for (int k0 = 0; k0 < DI; k0 += 32) {
        int r = tid >> 3, c = (tid & 7) << 2;
        float4 v = *(const float4*)(g_xc + (size_t)(tok0 + r) * DI + k0 + c);
        Xs[r][c] = v.x; Xs[r][c + 1] = v.y; Xs[r][c + 2] = v.z; Xs[r][c + 3] = v.w;
        #pragma unroll
        for (int q = 0; q < 4; q++) {
            int j = tid + q * 256;
            int k = j >> 5, oo = j & 31;
            Ws[k][oo] = (oo < 16) ? WB[(k0 + k) * DS + oo]
                                  : WC[(k0 + k) * DS + (oo - 16)];
        }
        __syncthreads();
        #pragma unroll
        for (int k = 0; k < 32; k++) {
            float wv = Ws[k][o];
            #pragma unroll
            for (int i = 0; i < 4; i++)
                acc[i] = fmaf(Xs[tr + 8 * i][k], wv, acc[i]);
        }
        __syncthreads();
    }
    #pragma unroll
    for (int i = 0; i < 4; i++) {
        int token = tok0 + tr + 8 * i;
        if (o < 16) g_Bt[token * DS + o]        = acc[i] + bB[o];
        else        g_Ct[token * DS + (o - 16)] = acc[i] + bC[o - 16];
    }
}

// ---------------- 5. scan pass 1: chunk-local end states ----------------
__global__ void scan1_kernel(const float* __restrict__ A) {
    __shared__ float sB[CHL][DS];
    int tid = threadIdx.x;                  // 128
    int d  = blockIdx.x * 128 + tid;
    int ch = blockIdx.y, bb = blockIdx.z;
    int tok0 = bb * T_ + ch * CHL;
    float* sBf = &sB[0][0];
    #pragma unroll
    for (int q = 0; q < 8; q++)
        sBf[tid + q * 128] = g_Bt[tok0 * DS + tid + q * 128];
    float a[DS], h[DS];
    #pragma unroll
    for (int s = 0; s < DS; s++) {
        a[s] = sigmoidf_(A[d * DS + s]);
        h[s] = 0.f;
    }
    __syncthreads();
    for (int t = 0; t < CHL; t++) {
        float x = g_xc[(size_t)(tok0 + t) * DI + d];
        #pragma unroll
        for (int s = 0; s < DS; s++)
            h[s] = fmaf(a[s], h[s], sB[t][s] * x);
    }
    float* ep = g_E + ((size_t)(bb * NCH + ch) * DI + d) * DS;
    #pragma unroll
    for (int s = 0; s < DS; s++) ep[s] = h[s];
}

// ---------------- 6. serial carry across chunks (a is time-invariant) ----------------
__global__ void carry_kernel(const float* __restrict__ A) {
    int idx = blockIdx.x * 256 + threadIdx.x;  // < B_*DI
    int d = idx & (DI - 1), bb = idx >> 11;
    float aL[DS], st[DS];
    #pragma unroll
    for (int s = 0; s < DS; s++) {
        float a = sigmoidf_(A[d * DS + s]);
        #pragma unroll
        for (int r = 0; r < 6; r++) a *= a;    // a^64
        aL[s] = a;
        st[s] = 0.f;
    }
    for (int c = 0; c < NCH; c++) {
        float* sp = g_S + ((size_t)(bb * NCH + c) * DI + d) * DS;
        const float* ep = g_E + ((size_t)(bb * NCH + c) * DI + d) * DS;
        #pragma unroll
        for (int s = 0; s < DS; s++) sp[s] = st[s];
        #pragma unroll
        for (int s = 0; s < DS; s++) st[s] = fmaf(aL[s], st[s], ep[s]);
    }
}

// ---------------- 7. scan pass 2: full states + y = (h.C + D*xc)*silu(gate) ----------------
__global__ void scan2_kernel(const float* __restrict__ A,
                             const float* __restrict__ Dv) {
    __shared__ float sB[CHL][DS], sC[CHL][DS];
    int tid = threadIdx.x;                  // 128
    int d  = blockIdx.x * 128 + tid;
    int ch = blockIdx.y, bb = blockIdx.z;
    int tok0 = bb * T_ + ch * CHL;
    #pragma unroll
    for (int q = 0; q < 8; q++) {
        (&sB[0][0])[tid + q * 128] = g_Bt[tok0 * DS + tid + q * 128];
        (&sC[0][0])[tid + q * 128] = g_Ct[tok0 * DS + tid + q * 128];
    }
    const float* sp = g_S + ((size_t)(bb * NCH + ch) * DI + d) * DS;
    float a[DS], h[DS];
    #pragma unroll
    for (int s = 0; s < DS; s++) {
        a[s] = sigmoidf_(A[d * DS + s]);
        h[s] = sp[s];
    }
    float Dd = Dv[d];
    __syncthreads();
    for (int t = 0; t < CHL; t++) {
        int tok = tok0 + t;
        float x = g_xc[(size_t)tok * DI + d];
        float yv = Dd * x;
        #pragma unroll
        for (int s = 0; s < DS; s++) {
            h[s] = fmaf(a[s], h[s], sB[t][s] * x);
            yv = fmaf(h[s], sC[t][s], yv);
        }
        float gt = g_proj[(size_t)tok * (2 * DI) + DI + d];
        g_y[(size_t)tok * DI + d] = yv * siluf_(gt);
    }
}

// ---------------- launch ----------------
extern "C" void kernel_launch(void* const* d_in, const int* in_sizes, int n_in,
                              void* d_out, int out_size) {
    const float* x      = (const float*)d_in[0];
    const float* ln_g   = (const float*)d_in[1];
    const float* ln_b   = (const float*)d_in[2];
    const float* W_in   = (const float*)d_in[3];
    const float* b_in   = (const float*)d_in[4];
    const float* conv_w = (const float*)d_in[5];
    const float* conv_b = (const float*)d_in[6];
    const float* A      = (const float*)d_in[7];
    const float* W_B    = (const float*)d_in[8];
    const float* b_B    = (const float*)d_in[9];
    const float* W_C    = (const float*)d_in[10];
    const float* b_C    = (const float*)d_in[11];
    const float* Dv     = (const float*)d_in[12];
    const float* W_out  = (const float*)d_in[13];
    const float* b_out  = (const float*)d_in[14];
    float* out = (float*)d_out;

    void *pxn, *pproj, *py;
    cudaGetSymbolAddress(&pxn,  g_xn);
    cudaGetSymbolAddress(&pproj, g_proj);
    cudaGetSymbolAddress(&py,   g_y);

    ln_kernel<<<TOK, 256>>>(x, ln_g, ln_b);

    // proj = xn @ W_in + b_in   (2048 x 4096, K=1024)
    gemm_f32x2<0><<<dim3((2 * DI) / 128, TOK / 128), 256>>>(
        (const float*)pxn, W_in, b_in, (const float*)pxn /*unused*/,
        (float*)pproj, TOK, 2 * DI, DM);

    conv_silu_kernel<<<(TOK * DI) / 256, 256>>>(conv_w, conv_b);

    bc_kernel<<<TOK / 32, 256>>>(W_B, b_B, W_C, b_C);

    scan1_kernel<<<dim3(DI / 128, NCH, B_), 128>>>(A);
    carry_kernel<<<(B_ * DI) / 256, 256>>>(A);
    scan2_kernel<<<dim3(DI / 128, NCH, B_), 128>>>(A, Dv);

    // out = y @ W_out + b_out + x   (2048 x 1024, K=2048)
    gemm_f32x2<1><<<dim3(DM / 128, TOK / 128), 256>>>(
        (const float*)py, W_out, b_out, x, out, TOK, DM, DI);
}

// round 6
// speedup vs baseline: 2.3335x; 2.3335x over previous
#include <cuda_runtime.h>
#include <cstdint>

// ---------------- problem constants ----------------
#define B_   2
#define T_   1024
#define DM   1024      // d_model
#define DI   2048      // d_inner
#define DS   16        // d_state
#define TOK  (B_ * T_) // 2048 tokens
#define NCH  16        // scan chunks
#define CHL  64        // chunk length
#define KSL  8         // bc split-K slices

// ---------------- scratch (static device memory) ----------------
__device__ float g_xn  [TOK * DM];
__device__ float g_proj[TOK * 2 * DI];
__device__ float g_xc  [TOK * DI];
__device__ float g_Bt  [TOK * DS];
__device__ float g_Ct  [TOK * DS];
__device__ float g_E   [B_ * NCH * DI * DS];
__device__ float g_S   [B_ * NCH * DI * DS];
__device__ float g_y   [TOK * DI];
__device__ float g_BCp [KSL][TOK][32];

__device__ __forceinline__ float sigmoidf_(float x) { return 1.0f / (1.0f + __expf(-x)); }
__device__ __forceinline__ float siluf_(float x)    { return x / (1.0f + __expf(-x)); }

// ---------------- 1. LayerNorm ----------------
__global__ void ln_kernel(const float* __restrict__ x,
                          const float* __restrict__ g,
                          const float* __restrict__ b) {
    int row = blockIdx.x;
    int tid = threadIdx.x;
    const float4* xr = (const float4*)(x + (size_t)row * DM);
    float4 v = xr[tid];
    float s = v.x + v.y + v.z + v.w;
    float q = v.x * v.x + v.y * v.y + v.z * v.z + v.w * v.w;
    #pragma unroll
    for (int o = 16; o; o >>= 1) {
        s += __shfl_down_sync(0xFFFFFFFFu, s, o);
        q += __shfl_down_sync(0xFFFFFFFFu, q, o);
    }
    __shared__ float ss[8], sq[8];
    __shared__ float smu, srstd;
    int w = tid >> 5, l = tid & 31;
    if (l == 0) { ss[w] = s; sq[w] = q; }
    __syncthreads();
    if (tid == 0) {
        float S = 0.f, Q = 0.f;
        #pragma unroll
        for (int i = 0; i < 8; i++) { S += ss[i]; Q += sq[i]; }
        float mu = S * (1.0f / DM);
        float var = Q * (1.0f / DM) - mu * mu;
        smu = mu; srstd = rsqrtf(var + 1e-5f);
    }
    __syncthreads();
    float mu = smu, rstd = srstd;
    float4 gv = ((const float4*)g)[tid];
    float4 bv = ((const float4*)b)[tid];
    float4 o;
    o.x = (v.x - mu) * rstd * gv.x + bv.x;
    o.y = (v.y - mu) * rstd * gv.y + bv.y;
    o.z = (v.z - mu) * rstd * gv.z + bv.z;
    o.w = (v.w - mu) * rstd * gv.w + bv.w;
    ((float4*)(g_xn + (size_t)row * DM))[tid] = o;
}

// ---------------- tf32 mma.sync GEMM: C = A @ B + bias (+resid) ----------------
// A: MxK row-major.  B: KxN row-major.  C: MxN.  128x128 tile, K-step 32.
#define AST 36                       // A smem stride (floats): banks 4m+k, conflict-free
#define BST 136                      // B smem stride (floats): banks 8k+n, conflict-free
#define A_TILE_F (128 * AST)         // 4608 floats
#define B_TILE_F (32 * BST)          // 4352 floats
#define STAGE_F  (A_TILE_F + B_TILE_F)
#define SM_TOT   (2 * STAGE_F * 4)   // 71680 bytes

__device__ __forceinline__ void cp16(uint32_t dst, const void* src) {
    asm volatile("cp.async.cg.shared.global [%0], [%1], 16;"
                 :: "r"(dst), "l"(src) : "memory");
}
__device__ __forceinline__ uint32_t smem_u32(const void* p) {
    uint32_t a;
    asm("{ .reg .u64 t; cvta.to.shared.u64 t, %1; cvt.u32.u64 %0, t; }"
        : "=r"(a) : "l"(p));
    return a;
}
__device__ __forceinline__ void mma_tf32(float* c, const uint32_t* a, const uint32_t* b) {
    asm volatile(
        "mma.sync.aligned.m16n8k8.row.col.f32.tf32.tf32.f32 "
        "{%0,%1,%2,%3}, {%4,%5,%6,%7}, {%8,%9}, {%0,%1,%2,%3};"
        : "+f"(c[0]), "+f"(c[1]), "+f"(c[2]), "+f"(c[3])
        : "r"(a[0]), "r"(a[1]), "r"(a[2]), "r"(a[3]), "r"(b[0]), "r"(b[1]));
}

template <int EPI>
__global__ __launch_bounds__(256, 2) void gemm_tf32(
    const float* __restrict__ Amat, const float* __restrict__ Bmat,
    const float* __restrict__ bias, const float* __restrict__ resid,
    float* __restrict__ Cmat, int M, int N, int K)
{
    extern __shared__ float sm[];
    float* As[2] = {sm, sm + STAGE_F};
    float* Bs[2] = {sm + A_TILE_F, sm + STAGE_F + A_TILE_F};
    uint32_t sbase = smem_u32(sm);

    int tid  = threadIdx.x;
    int wid  = tid >> 5, lane = tid & 31;
    int wm   = wid >> 2, wn = wid & 3;      // warp grid 2(m) x 4(n)
    int gid  = lane >> 2, tig = lane & 3;
    int mBase = blockIdx.y * 128, nBase = blockIdx.x * 128;
    const int S = K / 32;

    float acc[4][4][4];
    #pragma unroll
    for (int i = 0; i < 4; i++)
        #pragma unroll
        for (int j = 0; j < 4; j++)
            #pragma unroll
            for (int c = 0; c < 4; c++) acc[i][j][c] = 0.f;

    // stage loader (cp.async both tiles)
    auto stage_load = [&](int buf, int k0) {
        uint32_t aBase = sbase + (buf ? STAGE_F * 4 : 0);
        uint32_t bBase = aBase + A_TILE_F * 4;
        #pragma unroll
        for (int q = 0; q < 4; q++) {                 // A: 128x32
            int lin = tid + q * 256;
            int m = lin >> 3, c = lin & 7;
            cp16(aBase + (m * AST + c * 4) * 4,
                 Amat + (size_t)(mBase + m) * K + k0 + c * 4);
        }
        #pragma unroll
        for (int q = 0; q < 4; q++) {                 // B: 32x128
            int lin = tid + q * 256;
            int k = lin >> 5, c = lin & 31;
            cp16(bBase + (k * BST + c * 4) * 4,
                 Bmat + (size_t)(k0 + k) * N + nBase + c * 4);
        }
        asm volatile("cp.async.commit_group;" ::: "memory");
    };

    stage_load(0, 0);
    for (int s = 0; s < S; s++) {
        if (s + 1 < S) {
            stage_load((s + 1) & 1, (s + 1) * 32);
            asm volatile("cp.async.wait_group 1;" ::: "memory");
        } else {
            asm volatile("cp.async.wait_group 0;" ::: "memory");
        }
        __syncthreads();

        const float* Ab = As[s & 1];
        const float* Bb = Bs[s & 1];
        #pragma unroll
        for (int k8 = 0; k8 < 4; k8++) {
            int kb = k8 * 8;
            uint32_t a[4][4], b[4][2];
            #pragma unroll
            for (int mt = 0; mt < 4; mt++) {
                const float* ap = Ab + (wm * 64 + mt * 16 + gid) * AST + kb + tig;
                a[mt][0] = __float_as_uint(ap[0]);
                a[mt][1] = __float_as_uint(ap[8 * AST]);
                a[mt][2] = __float_as_uint(ap[4]);
                a[mt][3] = __float_as_uint(ap[8 * AST + 4]);
            }
            #pragma unroll
            for (int nt = 0; nt < 4; nt++) {
                const float* bp = Bb + (kb + tig) * BST + wn * 32 + nt * 8 + gid;
                b[nt][0] = __float_as_uint(bp[0]);
                b[nt][1] = __float_as_uint(bp[4 * BST]);
            }
            #pragma unroll
            for (int mt = 0; mt < 4; mt++)
                #pragma unroll
                for (int nt = 0; nt < 4; nt++)
                    mma_tf32(acc[mt][nt], a[mt], b[nt]);
        }
        __syncthreads();
    }

    // epilogue
    #pragma unroll
    for (int mt = 0; mt < 4; mt++) {
        int r0 = mBase + wm * 64 + mt * 16 + gid;
        #pragma unroll
        for (int nt = 0; nt < 4; nt++) {
            int cN = nBase + wn * 32 + nt * 8 + tig * 2;
            float2 bv = *(const float2*)(bias + cN);
            float2 o0, o1;
            o0.x = acc[mt][nt][0] + bv.x;
            o0.y = acc[mt][nt][1] + bv.y;
            o1.x = acc[mt][nt][2] + bv.x;
            o1.y = acc[mt][nt][3] + bv.y;
            if (EPI) {
                float2 rv0 = *(const float2*)(resid + (size_t)r0 * N + cN);
                float2 rv1 = *(const float2*)(resid + (size_t)(r0 + 8) * N + cN);
                o0.x += rv0.x; o0.y += rv0.y;
                o1.x += rv1.x; o1.y += rv1.y;
            }
            *(float2*)(Cmat + (size_t)r0 * N + cN) = o0;
            *(float2*)(Cmat + (size_t)(r0 + 8) * N + cN) = o1;
        }
    }
}

// ---------------- 3. depthwise causal conv1d + silu ----------------
__global__ void conv_silu_kernel(const float* __restrict__ cw,
                                 const float* __restrict__ cb) {
    int i = blockIdx.x * 256 + threadIdx.x;
    int d   = i & (DI - 1);
    int tok = i >> 11;
    int t   = tok & (T_ - 1);
    float4 w = *(const float4*)(cw + d * 4);
    const float* base = g_proj + (size_t)tok * (2 * DI) + d;
    float acc = cb[d];
    if (t >= 3) acc = fmaf(w.x, base[-3 * 2 * DI], acc);
    if (t >= 2) acc = fmaf(w.y, base[-2 * 2 * DI], acc);
    if (t >= 1) acc = fmaf(w.z, base[-1 * 2 * DI], acc);
    acc = fmaf(w.w, base[0], acc);
    g_xc[i] = siluf_(acc);
}

// ---------------- 4. B_t / C_t split-K partials + reduce ----------------
__global__ __launch_bounds__(256) void bc_part_kernel(
    const float* __restrict__ WB, const float* __restrict__ WC)
{
    __shared__ float Xs[32][33];
    __shared__ float Ws[32][32];
    int tid = threadIdx.x;
    int tok0 = blockIdx.x * 32;
    int kBase = blockIdx.y * (DI / KSL);
    int o = tid & 31, tr = tid >> 5;
    float acc[4] = {0.f, 0.f, 0.f, 0.f};
    for (int k0 = kBase; k0 < kBase + DI / KSL; k0 += 32) {
        int r = tid >> 3, c = (tid & 7) << 2;
        float4 v = *(const float4*)(g_xc + (size_t)(tok0 + r) * DI + k0 + c);
        Xs[r][c] = v.x; Xs[r][c + 1] = v.y; Xs[r][c + 2] = v.z; Xs[r][c + 3] = v.w;
        #pragma unroll
        for (int q = 0; q < 4; q++) {
            int j = tid + q * 256;
            int k = j >> 5, oo = j & 31;
            Ws[k][oo] = (oo < 16) ? WB[(k0 + k) * DS + oo]
                                  : WC[(k0 + k) * DS + (oo - 16)];
        }
        __syncthreads();
        #pragma unroll
        for (int k = 0; k < 32; k++) {
            float wv = Ws[k][o];
            #pragma unroll
            for (int i = 0; i < 4; i++)
                acc[i] = fmaf(Xs[tr + 8 * i][k], wv, acc[i]);
        }
        __syncthreads();
    }
    #pragma unroll
    for (int i = 0; i < 4; i++)
        g_BCp[blockIdx.y][tok0 + tr + 8 * i][o] = acc[i];
}

__global__ void bc_reduce_kernel(const float* __restrict__ bB,
                                 const float* __restrict__ bC) {
    int idx = blockIdx.x * 256 + threadIdx.x;   // TOK*32
    int o = idx & 31, tok = idx >> 5;
    float s = 0.f;
    #pragma unroll
    for (int p = 0; p < KSL; p++) s += g_BCp[p][tok][o];
    if (o < 16) g_Bt[tok * DS + o]        = s + bB[o];
    else        g_Ct[tok * DS + (o - 16)] = s + bC[o - 16];
}

// ---------------- 5. scan pass 1: chunk-local end states ----------------
__global__ void scan1_kernel(const float* __restrict__ A) {
    __shared__ float sB[CHL][DS];
    int tid = threadIdx.x;
    int d  = blockIdx.x * 128 + tid;
    int ch = blockIdx.y, bb = blockIdx.z;
    int tok0 = bb * T_ + ch * CHL;
    float* sBf = &sB[0][0];
    #pragma unroll
    for (int q = 0; q < 8; q++)
        sBf[tid + q * 128] = g_Bt[tok0 * DS + tid + q * 128];
    float a[DS], h[DS];
    #pragma unroll
    for (int s = 0; s < DS; s++) {
        a[s] = sigmoidf_(A[d * DS + s]);
        h[s] = 0.f;
    }
    __syncthreads();
    for (int t = 0; t < CHL; t++) {
        float x = g_xc[(size_t)(tok0 + t) * DI + d];
        #pragma unroll
        for (int s = 0; s < DS; s++)
            h[s] = fmaf(a[s], h[s], sB[t][s] * x);
    }
    float* ep = g_E + ((size_t)(bb * NCH + ch) * DI + d) * DS;
    #pragma unroll
    for (int s = 0; s < DS; s++) ep[s] = h[s];
}

// ---------------- 6. serial carry across chunks ----------------
__global__ void carry_kernel(const float* __restrict__ A) {
    int idx = blockIdx.x * 256 + threadIdx.x;
    int d = idx & (DI - 1), bb = idx >> 11;
    float aL[DS], st[DS];
    #pragma unroll
    for (int s = 0; s < DS; s++) {
        float a = sigmoidf_(A[d * DS + s]);
        #pragma unroll
        for (int r = 0; r < 6; r++) a *= a;   // a^64
        aL[s] = a;
        st[s] = 0.f;
    }
    for (int c = 0; c < NCH; c++) {
        float* sp = g_S + ((size_t)(bb * NCH + c) * DI + d) * DS;
        const float* ep = g_E + ((size_t)(bb * NCH + c) * DI + d) * DS;
        #pragma unroll
        for (int s = 0; s < DS; s++) sp[s] = st[s];
        #pragma unroll
        for (int s = 0; s < DS; s++) st[s] = fmaf(aL[s], st[s], ep[s]);
    }
}

// ---------------- 7. scan pass 2 + epilogue ----------------
__global__ void scan2_kernel(const float* __restrict__ A,
                             const float* __restrict__ Dv) {
    __shared__ float sB[CHL][DS], sC[CHL][DS];
    int tid = threadIdx.x;
    int d  = blockIdx.x * 128 + tid;
    int ch = blockIdx.y, bb = blockIdx.z;
    int tok0 = bb * T_ + ch * CHL;
    #pragma unroll
    for (int q = 0; q < 8; q++) {
        (&sB[0][0])[tid + q * 128] = g_Bt[tok0 * DS + tid + q * 128];
        (&sC[0][0])[tid + q * 128] = g_Ct[tok0 * DS + tid + q * 128];
    }
    const float* sp = g_S + ((size_t)(bb * NCH + ch) * DI + d) * DS;
    float a[DS], h[DS];
    #pragma unroll
    for (int s = 0; s < DS; s++) {
        a[s] = sigmoidf_(A[d * DS + s]);
        h[s] = sp[s];
    }
    float Dd = Dv[d];
    __syncthreads();
    for (int t = 0; t < CHL; t++) {
        int tok = tok0 + t;
        float x = g_xc[(size_t)tok * DI + d];
        float yv = Dd * x;
        #pragma unroll
        for (int s = 0; s < DS; s++) {
            h[s] = fmaf(a[s], h[s], sB[t][s] * x);
            yv = fmaf(h[s], sC[t][s], yv);
        }
        float gt = g_proj[(size_t)tok * (2 * DI) + DI + d];
        g_y[(size_t)tok * DI + d] = yv * siluf_(gt);
    }
}

// ---------------- launch ----------------
extern "C" void kernel_launch(void* const* d_in, const int* in_sizes, int n_in,
                              void* d_out, int out_size) {
    const float* x      = (const float*)d_in[0];
    const float* ln_g   = (const float*)d_in[1];
    const float* ln_b   = (const float*)d_in[2];
    const float* W_in   = (const float*)d_in[3];
    const float* b_in   = (const float*)d_in[4];
    const float* conv_w = (const float*)d_in[5];
    const float* conv_b = (const float*)d_in[6];
    const float* A      = (const float*)d_in[7];
    const float* W_B    = (const float*)d_in[8];
    const float* b_B    = (const float*)d_in[9];
    const float* W_C    = (const float*)d_in[10];
    const float* b_C    = (const float*)d_in[11];
    const float* Dv     = (const float*)d_in[12];
    const float* W_out  = (const float*)d_in[13];
    const float* b_out  = (const float*)d_in[14];
    float* out = (float*)d_out;

    void *pxn, *pproj, *py;
    cudaGetSymbolAddress(&pxn,  g_xn);
    cudaGetSymbolAddress(&pproj, g_proj);
    cudaGetSymbolAddress(&py,   g_y);

    cudaFuncSetAttribute(gemm_tf32<0>, cudaFuncAttributeMaxDynamicSharedMemorySize, SM_TOT);
    cudaFuncSetAttribute(gemm_tf32<1>, cudaFuncAttributeMaxDynamicSharedMemorySize, SM_TOT);

    ln_kernel<<<TOK, 256>>>(x, ln_g, ln_b);

    // proj = xn @ W_in + b_in    (M=2048, N=4096, K=1024)
    gemm_tf32<0><<<dim3((2 * DI) / 128, TOK / 128), 256, SM_TOT>>>(
        (const float*)pxn, W_in, b_in, (const float*)pxn,
        (float*)pproj, TOK, 2 * DI, DM);

    conv_silu_kernel<<<(TOK * DI) / 256, 256>>>(conv_w, conv_b);

    bc_part_kernel<<<dim3(TOK / 32, KSL), 256>>>(W_B, W_C);
    bc_reduce_kernel<<<(TOK * 32) / 256, 256>>>(b_B, b_C);

    scan1_kernel<<<dim3(DI / 128, NCH, B_), 128>>>(A);
    carry_kernel<<<(B_ * DI) / 256, 256>>>(A);
    scan2_kernel<<<dim3(DI / 128, NCH, B_), 128>>>(A, Dv);

    // out = y @ W_out + b_out + x   (M=2048, N=1024, K=2048)
    gemm_tf32<1><<<dim3(DM / 128, TOK / 128), 256, SM_TOT>>>(
        (const float*)py, W_out, b_out, x, out, TOK, DM, DI);
}

// round 7
// speedup vs baseline: 3.1664x; 1.3569x over previous
#include <cuda_runtime.h>
#include <cuda_fp16.h>
#include <cstdint>

// ---------------- problem constants ----------------
#define B_   2
#define T_   1024
#define DM   1024      // d_model
#define DI   2048      // d_inner
#define DS   16        // d_state
#define TOK  (B_ * T_) // 2048 tokens
#define NCH  32        // scan chunks
#define CHL  32        // chunk length
#define KSL  8         // bc split-K slices

// ---------------- scratch (static device memory) ----------------
__device__ __half g_xnh [TOK * DM];            // fp16 LN output (gemm1 A)
__device__ __half g_WinH[DM * 2 * DI];         // fp16 W_in
__device__ __half g_WoutH[DI * DM];            // fp16 W_out
__device__ __half g_WBC [DI * 32];             // fp16 [W_B | W_C]
__device__ float  g_proj[TOK * 2 * DI];        // in_proj output (xp | gate), fp32
__device__ float  g_xc  [TOK * DI];            // conv+silu output fp32
__device__ __half g_xch [TOK * DI];            // conv+silu output fp16 (bc A)
__device__ float  g_Bt  [TOK * DS];
__device__ float  g_Ct  [TOK * DS];
__device__ float  g_E   [B_ * NCH * DI * DS];
__device__ float  g_S   [B_ * NCH * DI * DS];
__device__ __half g_y   [TOK * DI];            // gated SSM output fp16 (gemm2 A)
__device__ float  g_BCp [KSL][TOK][32];

__device__ __forceinline__ float sigmoidf_(float x) { return 1.0f / (1.0f + __expf(-x)); }
__device__ __forceinline__ float siluf_(float x)    { return x / (1.0f + __expf(-x)); }

__device__ __forceinline__ uint32_t smem_u32(const void* p) {
    uint32_t a;
    asm("{ .reg .u64 t; cvta.to.shared.u64 t, %1; cvt.u32.u64 %0, t; }"
        : "=r"(a) : "l"(p));
    return a;
}
__device__ __forceinline__ void cp16(uint32_t dst, const void* src) {
    asm volatile("cp.async.cg.shared.global [%0], [%1], 16;"
                 :: "r"(dst), "l"(src) : "memory");
}
__device__ __forceinline__ void ldsm4(uint32_t* r, uint32_t addr) {
    asm volatile("ldmatrix.sync.aligned.m8n8.x4.shared.b16 {%0,%1,%2,%3}, [%4];"
        : "=r"(r[0]), "=r"(r[1]), "=r"(r[2]), "=r"(r[3]) : "r"(addr));
}
__device__ __forceinline__ void ldsm4t(uint32_t* r, uint32_t addr) {
    asm volatile("ldmatrix.sync.aligned.m8n8.x4.trans.shared.b16 {%0,%1,%2,%3}, [%4];"
        : "=r"(r[0]), "=r"(r[1]), "=r"(r[2]), "=r"(r[3]) : "r"(addr));
}
__device__ __forceinline__ void mma_f16(float* c, const uint32_t* a, const uint32_t* b) {
    asm volatile(
        "mma.sync.aligned.m16n8k16.row.col.f32.f16.f16.f32 "
        "{%0,%1,%2,%3}, {%4,%5,%6,%7}, {%8,%9}, {%0,%1,%2,%3};"
        : "+f"(c[0]), "+f"(c[1]), "+f"(c[2]), "+f"(c[3])
        : "r"(a[0]), "r"(a[1]), "r"(a[2]), "r"(a[3]), "r"(b[0]), "r"(b[1]));
}

// ---------------- 1. LayerNorm (writes fp16) ----------------
__global__ void ln_kernel(const float* __restrict__ x,
                          const float* __restrict__ g,
                          const float* __restrict__ b) {
    int row = blockIdx.x;
    int tid = threadIdx.x;
    const float4* xr = (const float4*)(x + (size_t)row * DM);
    float4 v = xr[tid];
    float s = v.x + v.y + v.z + v.w;
    float q = v.x * v.x + v.y * v.y + v.z * v.z + v.w * v.w;
    #pragma unroll
    for (int o = 16; o; o >>= 1) {
        s += __shfl_down_sync(0xFFFFFFFFu, s, o);
        q += __shfl_down_sync(0xFFFFFFFFu, q, o);
    }
    __shared__ float ss[8], sq[8];
    __shared__ float smu, srstd;
    int w = tid >> 5, l = tid & 31;
    if (l == 0) { ss[w] = s; sq[w] = q; }
    __syncthreads();
    if (tid == 0) {
        float S = 0.f, Q = 0.f;
        #pragma unroll
        for (int i = 0; i < 8; i++) { S += ss[i]; Q += sq[i]; }
        float mu = S * (1.0f / DM);
        float var = Q * (1.0f / DM) - mu * mu;
        smu = mu; srstd = rsqrtf(var + 1e-5f);
    }
    __syncthreads();
    float mu = smu, rstd = srstd;
    float4 gv = ((const float4*)g)[tid];
    float4 bv = ((const float4*)b)[tid];
    __half2* orow = (__half2*)(g_xnh + (size_t)row * DM);
    orow[tid * 2]     = __floats2half2_rn((v.x - mu) * rstd * gv.x + bv.x,
                                          (v.y - mu) * rstd * gv.y + bv.y);
    orow[tid * 2 + 1] = __floats2half2_rn((v.z - mu) * rstd * gv.z + bv.z,
                                          (v.w - mu) * rstd * gv.w + bv.w);
}

// ---------------- weight converts ----------------
__global__ void f2h_kernel(const float* __restrict__ src, __half* __restrict__ dst) {
    int i = blockIdx.x * 256 + threadIdx.x;   // over n/4
    float4 v = ((const float4*)src)[i];
    ((__half2*)dst)[i * 2]     = __floats2half2_rn(v.x, v.y);
    ((__half2*)dst)[i * 2 + 1] = __floats2half2_rn(v.z, v.w);
}
__global__ void pack_wbc_kernel(const float* __restrict__ WB,
                                const float* __restrict__ WC) {
    int i = blockIdx.x * 256 + threadIdx.x;   // DI*32
    int k = i >> 5, o = i & 31;
    float v = (o < 16) ? WB[k * DS + o] : WC[k * DS + (o - 16)];
    g_WBC[i] = __float2half(v);
}

// ---------------- fp16 mma GEMM: C = A @ B + bias (+resid) ----------------
// A: MxK fp16 row-major.  B: KxN fp16 row-major.  C: MxN fp32.  128x128 tile, K-step 32.
#define GA_ST 80                    // A smem row stride bytes (32 fp16 + pad)
#define GB_ST 272                   // B smem row stride bytes (128 fp16 + pad)
#define GA_BYTES (128 * GA_ST)      // 10240
#define GB_BYTES (32 * GB_ST)       // 8704
#define GSTAGE (GA_BYTES + GB_BYTES)
#define GSM (3 * GSTAGE)            // 56832

template <int EPI>
__global__ __launch_bounds__(256) void gemm_f16(
    const __half* __restrict__ Amat, const __half* __restrict__ Bmat,
    const float* __restrict__ bias, const float* __restrict__ resid,
    float* __restrict__ Cmat, int M, int N, int K)
{
    extern __shared__ char sm[];
    uint32_t sb = smem_u32(sm);
    int tid = threadIdx.x;
    int wid = tid >> 5, lane = tid & 31;
    int wm = wid >> 2, wn = wid & 3;       // 2(m) x 4(n) warps
    int gid = lane >> 2, tig = lane & 3;
    int mBase = blockIdx.y * 128, nBase = blockIdx.x * 128;
    const int S = K / 32;

    float acc[4][4][4];
    #pragma unroll
    for (int i = 0; i < 4; i++)
        #pragma unroll
        for (int j = 0; j < 4; j++)
            #pragma unroll
            for (int c = 0; c < 4; c++) acc[i][j][c] = 0.f;

    auto stage_load = [&](int buf, int k0) {
        uint32_t ab = sb + buf * GSTAGE;
        uint32_t bb = ab + GA_BYTES;
        #pragma unroll
        for (int q = 0; q < 2; q++) {               // A: 128 rows x 4 chunks
            int lin = tid + q * 256;
            int row = lin >> 2, ch = lin & 3;
            cp16(ab + row * GA_ST + ch * 16,
                 Amat + (size_t)(mBase + row) * K + k0 + ch * 8);
        }
        #pragma unroll
        for (int q = 0; q < 2; q++) {               // B: 32 rows x 16 chunks
            int lin = tid + q * 256;
            int row = lin >> 4, ch = lin & 15;
            cp16(bb + row * GB_ST + ch * 16,
                 Bmat + (size_t)(k0 + row) * N + nBase + ch * 8);
        }
        asm volatile("cp.async.commit_group;" ::: "memory");
    };

    stage_load(0, 0);
    stage_load(1, 32);
    for (int s = 0; s < S; s++) {
        asm volatile("cp.async.wait_group 1;" ::: "memory");
        __syncthreads();
        if (s + 2 < S) stage_load((s + 2) % 3, (s + 2) * 32);

        uint32_t ab = sb + (s % 3) * GSTAGE;
        uint32_t bb = ab + GA_BYTES;
        #pragma unroll
        for (int k16 = 0; k16 < 2; k16++) {
            uint32_t af[4][4], bf[2][4];
            #pragma unroll
            for (int mt = 0; mt < 4; mt++) {
                uint32_t addr = ab + (wm * 64 + mt * 16 + (lane & 15)) * GA_ST
                              + k16 * 32 + ((lane >> 4) << 4);
                ldsm4(af[mt], addr);
            }
            #pragma unroll
            for (int bt = 0; bt < 2; bt++) {
                uint32_t addr = bb + (k16 * 16 + (lane & 15)) * GB_ST
                              + (wn * 32 + bt * 16 + ((lane >> 4) << 3)) * 2;
                ldsm4t(bf[bt], addr);
            }
            #pragma unroll
            for (int mt = 0; mt < 4; mt++)
                #pragma unroll
                for (int nt = 0; nt < 4; nt++)
                    mma_f16(acc[mt][nt], af[mt], &bf[nt >> 1][(nt & 1) * 2]);
        }
    }

    #pragma unroll
    for (int mt = 0; mt < 4; mt++) {
        int r0 = mBase + wm * 64 + mt * 16 + gid;
        #pragma unroll
        for (int nt = 0; nt < 4; nt++) {
            int cN = nBase + wn * 32 + nt * 8 + tig * 2;
            float2 bv = *(const float2*)(bias + cN);
            float2 o0, o1;
            o0.x = acc[mt][nt][0] + bv.x;
            o0.y = acc[mt][nt][1] + bv.y;
            o1.x = acc[mt][nt][2] + bv.x;
            o1.y = acc[mt][nt][3] + bv.y;
            if (EPI) {
                float2 rv0 = *(const float2*)(resid + (size_t)r0 * N + cN);
                float2 rv1 = *(const float2*)(resid + (size_t)(r0 + 8) * N + cN);
                o0.x += rv0.x; o0.y += rv0.y;
                o1.x += rv1.x; o1.y += rv1.y;
            }
            *(float2*)(Cmat + (size_t)r0 * N + cN) = o0;
            *(float2*)(Cmat + (size_t)(r0 + 8) * N + cN) = o1;
        }
    }
}

// ---------------- 3. depthwise causal conv1d + silu (fp32 + fp16 out) ----------------
__global__ void conv_silu_kernel(const float* __restrict__ cw,
                                 const float* __restrict__ cb) {
    int i = blockIdx.x * 256 + threadIdx.x;
    int d   = i & (DI - 1);
    int tok = i >> 11;
    int t   = tok & (T_ - 1);
    float4 w = *(const float4*)(cw + d * 4);
    const float* base = g_proj + (size_t)tok * (2 * DI) + d;
    float acc = cb[d];
    if (t >= 3) acc = fmaf(w.x, base[-3 * 2 * DI], acc);
    if (t >= 2) acc = fmaf(w.y, base[-2 * 2 * DI], acc);
    if (t >= 1) acc = fmaf(w.z, base[-1 * 2 * DI], acc);
    acc = fmaf(w.w, base[0], acc);
    float v = siluf_(acc);
    g_xc[i]  = v;
    g_xch[i] = __float2half(v);
}

// ---------------- 4. B_t / C_t: fp16 mma split-K GEMM (M=TOK, N=32, K=DI) ----------------
#define CA_BYTES (128 * 80)         // 10240
#define CB_BYTES (32 * 80)          // 2560
#define CSTAGE (CA_BYTES + CB_BYTES)
#define CSM (3 * CSTAGE)            // 38400

__global__ __launch_bounds__(256) void bc_mma_kernel() {
    extern __shared__ char sm[];
    uint32_t sb = smem_u32(sm);
    int tid = threadIdx.x;
    int wid = tid >> 5, lane = tid & 31;
    int wm = wid >> 1, wn = wid & 1;       // 4(m) x 2(n) warps; warp tile 32x16
    int gid = lane >> 2, tig = lane & 3;
    int tok0 = blockIdx.x * 128;
    int kBase = blockIdx.y * (DI / KSL);   // 256-wide K slice
    const __half* X = g_xch;
    const __half* W = g_WBC;

    float acc[2][2][4];
    #pragma unroll
    for (int i = 0; i < 2; i++)
        #pragma unroll
        for (int j = 0; j < 2; j++)
            #pragma unroll
            for (int c = 0; c < 4; c++) acc[i][j][c] = 0.f;

    auto stage_load = [&](int buf, int k0) {
        uint32_t ab = sb + buf * CSTAGE;
        uint32_t bb = ab + CA_BYTES;
        #pragma unroll
        for (int q = 0; q < 2; q++) {             // A: 128 rows x 4 chunks
            int lin = tid + q * 256;
            int row = lin >> 2, ch = lin & 3;
            cp16(ab + row * 80 + ch * 16,
                 X + (size_t)(tok0 + row) * DI + kBase + k0 + ch * 8);
        }
        if (tid < 128) {                          // B: 32 rows x 4 chunks
            int row = tid >> 2, ch = tid & 3;
            cp16(bb + row * 80 + ch * 16,
                 W + (size_t)(kBase + k0 + row) * 32 + ch * 8);
        }
        asm volatile("cp.async.commit_group;" ::: "memory");
    };

    const int S = (DI / KSL) / 32;   // 8
    stage_load(0, 0);
    stage_load(1, 32);
    for (int s = 0; s < S; s++) {
        asm volatile("cp.async.wait_group 1;" ::: "memory");
        __syncthreads();
        if (s + 2 < S) stage_load((s + 2) % 3, (s + 2) * 32);

        uint32_t ab = sb + (s % 3) * CSTAGE;
        uint32_t bb = ab + CA_BYTES;
        #pragma unroll
        for (int k16 = 0; k16 < 2; k16++) {
            uint32_t af[2][4], bf[4];
            #pragma unroll
            for (int mt = 0; mt < 2; mt++) {
                uint32_t addr = ab + (wm * 32 + mt * 16 + (lane & 15)) * 80
                              + k16 * 32 + ((lane >> 4) << 4);
                ldsm4(af[mt], addr);
            }
            {
                uint32_t addr = bb + (k16 * 16 + (lane & 15)) * 80
                              + (wn * 16 + ((lane >> 4) << 3)) * 2;
                ldsm4t(bf, addr);
            }
            #pragma unroll
            for (int mt = 0; mt < 2; mt++)
                #pragma unroll
                for (int nt = 0; nt < 2; nt++)
                    mma_f16(acc[mt][nt], af[mt], &bf[nt * 2]);
        }
    }

    #pragma unroll
    for (int mt = 0; mt < 2; mt++) {
        int r0 = tok0 + wm * 32 + mt * 16 + gid;
        #pragma unroll
        for (int nt = 0; nt < 2; nt++) {
            int o = wn * 16 + nt * 8 + tig * 2;
            *(float2*)&g_BCp[blockIdx.y][r0][o]     = make_float2(acc[mt][nt][0], acc[mt][nt][1]);
            *(float2*)&g_BCp[blockIdx.y][r0 + 8][o] = make_float2(acc[mt][nt][2], acc[mt][nt][3]);
        }
    }
}

__global__ void bc_reduce_kernel(const float* __restrict__ bB,
                                 const float* __restrict__ bC) {
    int idx = blockIdx.x * 256 + threadIdx.x;   // TOK*32
    int o = idx & 31, tok = idx >> 5;
    float s = 0.f;
    #pragma unroll
    for (int p = 0; p < KSL; p++) s += g_BCp[p][tok][o];
    if (o < 16) g_Bt[tok * DS + o]        = s + bB[o];
    else        g_Ct[tok * DS + (o - 16)] = s + bC[o - 16];
}

// ---------------- 5. scan pass 1: chunk-local end states ----------------
__global__ void scan1_kernel(const float* __restrict__ A) {
    __shared__ float sB[CHL][DS];
    int tid = threadIdx.x;                 // 128
    int d  = blockIdx.x * 128 + tid;
    int ch = blockIdx.y, bb = blockIdx.z;
    int tok0 = bb * T_ + ch * CHL;
    float* sBf = &sB[0][0];
    #pragma unroll
    for (int q = 0; q < (CHL * DS) / 128; q++)
        sBf[tid + q * 128] = g_Bt[tok0 * DS + tid + q * 128];
    float a[DS], h[DS];
    #pragma unroll
    for (int s = 0; s < DS; s++) {
        a[s] = sigmoidf_(A[d * DS + s]);
        h[s] = 0.f;
    }
    __syncthreads();
    for (int t = 0; t < CHL; t++) {
        float x = g_xc[(size_t)(tok0 + t) * DI + d];
        #pragma unroll
        for (int s = 0; s < DS; s++)
            h[s] = fmaf(a[s], h[s], sB[t][s] * x);
    }
    float* ep = g_E + ((size_t)(bb * NCH + ch) * DI + d) * DS;
    #pragma unroll
    for (int s = 0; s < DS; s++) ep[s] = h[s];
}

// ---------------- 6. serial carry across chunks ----------------
__global__ void carry_kernel(const float* __restrict__ A) {
    int idx = blockIdx.x * 256 + threadIdx.x;
    int d = idx & (DI - 1), bb = idx >> 11;
    float aL[DS], st[DS];
    #pragma unroll
    for (int s = 0; s < DS; s++) {
        float a = sigmoidf_(A[d * DS + s]);
        #pragma unroll
        for (int r = 0; r < 5; r++) a *= a;   // a^32 (CHL=32)
        aL[s] = a;
        st[s] = 0.f;
    }
    for (int c = 0; c < NCH; c++) {
        float* sp = g_S + ((size_t)(bb * NCH + c) * DI + d) * DS;
        const float* ep = g_E + ((size_t)(bb * NCH + c) * DI + d) * DS;
        #pragma unroll
        for (int s = 0; s < DS; s++) sp[s] = st[s];
        #pragma unroll
        for (int s = 0; s < DS; s++) st[s] = fmaf(aL[s], st[s], ep[s]);
    }
}

// ---------------- 7. scan pass 2 + gate epilogue (writes fp16 y) ----------------
__global__ void scan2_kernel(const float* __restrict__ A,
                             const float* __restrict__ Dv) {
    __shared__ float sB[CHL][DS], sC[CHL][DS];
    int tid = threadIdx.x;                 // 128
    int d  = blockIdx.x * 128 + tid;
    int ch = blockIdx.y, bb = blockIdx.z;
    int tok0 = bb * T_ + ch * CHL;
    #pragma unroll
    for (int q = 0; q < (CHL * DS) / 128; q++) {
        (&sB[0][0])[tid + q * 128] = g_Bt[tok0 * DS + tid + q * 128];
        (&sC[0][0])[tid + q * 128] = g_Ct[tok0 * DS + tid + q * 128];
    }
    const float* sp = g_S + ((size_t)(bb * NCH + ch) * DI + d) * DS;
    float a[DS], h[DS];
    #pragma unroll
    for (int s = 0; s < DS; s++) {
        a[s] = sigmoidf_(A[d * DS + s]);
        h[s] = sp[s];
    }
    float Dd = Dv[d];
    __syncthreads();
    for (int t = 0; t < CHL; t++) {
        int tok = tok0 + t;
        float x = g_xc[(size_t)tok * DI + d];
        float yv = Dd * x;
        #pragma unroll
        for (int s = 0; s < DS; s++) {
            h[s] = fmaf(a[s], h[s], sB[t][s] * x);
            yv = fmaf(h[s], sC[t][s], yv);
        }
        float gt = g_proj[(size_t)tok * (2 * DI) + DI + d];
        g_y[(size_t)tok * DI + d] = __float2half(yv * siluf_(gt));
    }
}

// ---------------- launch ----------------
extern "C" void kernel_launch(void* const* d_in, const int* in_sizes, int n_in,
                              void* d_out, int out_size) {
    const float* x      = (const float*)d_in[0];
    const float* ln_g   = (const float*)d_in[1];
    const float* ln_b   = (const float*)d_in[2];
    const float* W_in   = (const float*)d_in[3];
    const float* b_in   = (const float*)d_in[4];
    const float* conv_w = (const float*)d_in[5];
    const float* conv_b = (const float*)d_in[6];
    const float* A      = (const float*)d_in[7];
    const float* W_B    = (const float*)d_in[8];
    const float* b_B    = (const float*)d_in[9];
    const float* W_C    = (const float*)d_in[10];
    const float* b_C    = (const float*)d_in[11];
    const float* Dv     = (const float*)d_in[12];
    const float* W_out  = (const float*)d_in[13];
    const float* b_out  = (const float*)d_in[14];
    float* out = (float*)d_out;

    void *pxnh, *pproj, *py, *pwih, *pwoh;
    cudaGetSymbolAddress(&pxnh, g_xnh);
    cudaGetSymbolAddress(&pproj, g_proj);
    cudaGetSymbolAddress(&py,   g_y);
    cudaGetSymbolAddress(&pwih, g_WinH);
    cudaGetSymbolAddress(&pwoh, g_WoutH);

    cudaFuncSetAttribute(gemm_f16<0>, cudaFuncAttributeMaxDynamicSharedMemorySize, GSM);
    cudaFuncSetAttribute(gemm_f16<1>, cudaFuncAttributeMaxDynamicSharedMemorySize, GSM);
    cudaFuncSetAttribute(bc_mma_kernel, cudaFuncAttributeMaxDynamicSharedMemorySize, CSM);

    ln_kernel<<<TOK, 256>>>(x, ln_g, ln_b);
    f2h_kernel<<<(DM * 2 * DI) / 1024, 256>>>(W_in, (__half*)pwih);
    f2h_kernel<<<(DI * DM) / 1024, 256>>>(W_out, (__half*)pwoh);
    pack_wbc_kernel<<<(DI * 32) / 256, 256>>>(W_B, W_C);

    // proj = xn @ W_in + b_in    (M=2048, N=4096, K=1024)
    gemm_f16<0><<<dim3((2 * DI) / 128, TOK / 128), 256, GSM>>>(
        (const __half*)pxnh, (const __half*)pwih, b_in, x /*unused*/,
        (float*)pproj, TOK, 2 * DI, DM);

    conv_silu_kernel<<<(TOK * DI) / 256, 256>>>(conv_w, conv_b);

    bc_mma_kernel<<<dim3(TOK / 128, KSL), 256, CSM>>>();
    bc_reduce_kernel<<<(TOK * 32) / 256, 256>>>(b_B, b_C);

    scan1_kernel<<<dim3(DI / 128, NCH, B_), 128>>>(A);
    carry_kernel<<<(B_ * DI) / 256, 256>>>(A);
    scan2_kernel<<<dim3(DI / 128, NCH, B_), 128>>>(A, Dv);

    // out = y @ W_out + b_out + x   (M=2048, N=1024, K=2048)
    gemm_f16<1><<<dim3(DM / 128, TOK / 128), 256, GSM>>>(
        (const __half*)py, (const __half*)pwoh, b_out, x, out, TOK, DM, DI);
}

// round 8
// speedup vs baseline: 3.2339x; 1.0213x over previous
#include <cuda_runtime.h>
#include <cuda_fp16.h>
#include <cstdint>

// ---------------- problem constants ----------------
#define B_   2
#define T_   1024
#define DM   1024      // d_model
#define DI   2048      // d_inner
#define DS   16        // d_state
#define TOK  (B_ * T_) // 2048 tokens
#define NCH  32        // scan chunks
#define CHL  32        // chunk length
#define KSL  8         // bc split-K slices

// ---------------- scratch (static device memory) ----------------
__device__ __half g_xnh  [TOK * DM];        // fp16 LN output (gemm1 A)
__device__ __half g_WinH [DM * 2 * DI];     // fp16 W_in
__device__ __half g_WoutH[DI * DM];         // fp16 W_out
__device__ __half g_WBC  [DI * 32];         // fp16 [W_B | W_C]
__device__ __half g_projh[TOK * 2 * DI];    // in_proj output (xp | gate), fp16
__device__ __half g_xch  [TOK * DI];        // conv+silu output fp16
__device__ float  g_Bt   [TOK * DS];
__device__ float  g_Ct   [TOK * DS];
__device__ float  g_E    [B_ * NCH * DI * DS];
__device__ float  g_S    [B_ * NCH * DI * DS];
__device__ __half g_y    [TOK * DI];        // gated SSM output fp16 (gemm2 A)
__device__ float  g_BCp  [KSL][TOK][32];

__device__ __forceinline__ float sigmoidf_(float x) { return 1.0f / (1.0f + __expf(-x)); }
__device__ __forceinline__ float siluf_(float x)    { return x / (1.0f + __expf(-x)); }

__device__ __forceinline__ uint32_t smem_u32(const void* p) {
    uint32_t a;
    asm("{ .reg .u64 t; cvta.to.shared.u64 t, %1; cvt.u32.u64 %0, t; }"
        : "=r"(a) : "l"(p));
    return a;
}
__device__ __forceinline__ void cp16(uint32_t dst, const void* src) {
    asm volatile("cp.async.cg.shared.global [%0], [%1], 16;"
                 :: "r"(dst), "l"(src) : "memory");
}
__device__ __forceinline__ void ldsm4(uint32_t* r, uint32_t addr) {
    asm volatile("ldmatrix.sync.aligned.m8n8.x4.shared.b16 {%0,%1,%2,%3}, [%4];"
        : "=r"(r[0]), "=r"(r[1]), "=r"(r[2]), "=r"(r[3]) : "r"(addr));
}
__device__ __forceinline__ void ldsm4t(uint32_t* r, uint32_t addr) {
    asm volatile("ldmatrix.sync.aligned.m8n8.x4.trans.shared.b16 {%0,%1,%2,%3}, [%4];"
        : "=r"(r[0]), "=r"(r[1]), "=r"(r[2]), "=r"(r[3]) : "r"(addr));
}
__device__ __forceinline__ void mma_f16(float* c, const uint32_t* a, const uint32_t* b) {
    asm volatile(
        "mma.sync.aligned.m16n8k16.row.col.f32.f16.f16.f32 "
        "{%0,%1,%2,%3}, {%4,%5,%6,%7}, {%8,%9}, {%0,%1,%2,%3};"
        : "+f"(c[0]), "+f"(c[1]), "+f"(c[2]), "+f"(c[3])
        : "r"(a[0]), "r"(a[1]), "r"(a[2]), "r"(a[3]), "r"(b[0]), "r"(b[1]));
}

// ---------------- 1. LayerNorm (writes fp16) ----------------
__global__ void ln_kernel(const float* __restrict__ x,
                          const float* __restrict__ g,
                          const float* __restrict__ b) {
    int row = blockIdx.x;
    int tid = threadIdx.x;
    const float4* xr = (const float4*)(x + (size_t)row * DM);
    float4 v = xr[tid];
    float s = v.x + v.y + v.z + v.w;
    float q = v.x * v.x + v.y * v.y + v.z * v.z + v.w * v.w;
    #pragma unroll
    for (int o = 16; o; o >>= 1) {
        s += __shfl_down_sync(0xFFFFFFFFu, s, o);
        q += __shfl_down_sync(0xFFFFFFFFu, q, o);
    }
    __shared__ float ss[8], sq[8];
    __shared__ float smu, srstd;
    int w = tid >> 5, l = tid & 31;
    if (l == 0) { ss[w] = s; sq[w] = q; }
    __syncthreads();
    if (tid == 0) {
        float S = 0.f, Q = 0.f;
        #pragma unroll
        for (int i = 0; i < 8; i++) { S += ss[i]; Q += sq[i]; }
        float mu = S * (1.0f / DM);
        float var = Q * (1.0f / DM) - mu * mu;
        smu = mu; srstd = rsqrtf(var + 1e-5f);
    }
    __syncthreads();
    float mu = smu, rstd = srstd;
    float4 gv = ((const float4*)g)[tid];
    float4 bv = ((const float4*)b)[tid];
    __half2* orow = (__half2*)(g_xnh + (size_t)row * DM);
    orow[tid * 2]     = __floats2half2_rn((v.x - mu) * rstd * gv.x + bv.x,
                                          (v.y - mu) * rstd * gv.y + bv.y);
    orow[tid * 2 + 1] = __floats2half2_rn((v.z - mu) * rstd * gv.z + bv.z,
                                          (v.w - mu) * rstd * gv.w + bv.w);
}

// ---------------- weight converts ----------------
__global__ void f2h_kernel(const float* __restrict__ src, __half* __restrict__ dst) {
    int i = blockIdx.x * 256 + threadIdx.x;
    float4 v = ((const float4*)src)[i];
    ((__half2*)dst)[i * 2]     = __floats2half2_rn(v.x, v.y);
    ((__half2*)dst)[i * 2 + 1] = __floats2half2_rn(v.z, v.w);
}
__global__ void pack_wbc_kernel(const float* __restrict__ WB,
                                const float* __restrict__ WC) {
    int i = blockIdx.x * 256 + threadIdx.x;   // DI*32
    int k = i >> 5, o = i & 31;
    float v = (o < 16) ? WB[k * DS + o] : WC[k * DS + (o - 16)];
    g_WBC[i] = __float2half(v);
}

// ---------------- fp16 mma GEMM (templated tile): C = A @ B + bias (+resid) ----------------
// A: MxK fp16 row-major.  B: KxN fp16 row-major.  Block tile 128 x BN, K-step 32.
// Warp grid 2(m) x 4(n): warp tile 64 x BN/4.
#define GA_ST 80                    // A smem row stride bytes (32 fp16 + 8B pad)
#define GA_BYTES (128 * GA_ST)      // 10240

template <int EPI, int BN, typename OutT>
__global__ __launch_bounds__(256) void gemm_f16(
    const __half* __restrict__ Amat, const __half* __restrict__ Bmat,
    const float* __restrict__ bias, const float* __restrict__ resid,
    OutT* __restrict__ Cmat, int M, int N, int K)
{
    constexpr int GB_ST = BN * 2 + 16;            // B smem row stride bytes
    constexpr int GB_BYTES = 32 * GB_ST;
    constexpr int GSTAGE = GA_BYTES + GB_BYTES;
    constexpr int NT8 = BN / 32;                  // n8 sub-tiles per warp

    extern __shared__ char sm[];
    uint32_t sb = smem_u32(sm);
    int tid = threadIdx.x;
    int wid = tid >> 5, lane = tid & 31;
    int wm = wid >> 2, wn = wid & 3;
    int gid = lane >> 2, tig = lane & 3;
    int mBase = blockIdx.y * 128, nBase = blockIdx.x * BN;
    const int S = K / 32;

    float acc[4][NT8][4];
    #pragma unroll
    for (int i = 0; i < 4; i++)
        #pragma unroll
        for (int j = 0; j < NT8; j++)
            #pragma unroll
            for (int c = 0; c < 4; c++) acc[i][j][c] = 0.f;

    auto stage_load = [&](int buf, int k0) {
        uint32_t ab = sb + buf * GSTAGE;
        uint32_t bb = ab + GA_BYTES;
        #pragma unroll
        for (int q = 0; q < 2; q++) {                  // A: 128 rows x 4 chunks
            int lin = tid + q * 256;
            int row = lin >> 2, ch = lin & 3;
            cp16(ab + row * GA_ST + ch * 16,
                 Amat + (size_t)(mBase + row) * K + k0 + ch * 8);
        }
        #pragma unroll
        for (int q = 0; q < BN / 64; q++) {            // B: 32 rows x BN/8 chunks
            int lin = tid + q * 256;
            int row = lin / (BN / 8), ch = lin % (BN / 8);
            cp16(bb + row * GB_ST + ch * 16,
                 Bmat + (size_t)(k0 + row) * N + nBase + ch * 8);
        }
        asm volatile("cp.async.commit_group;" ::: "memory");
    };

    stage_load(0, 0);
    stage_load(1, 32);
    for (int s = 0; s < S; s++) {
        asm volatile("cp.async.wait_group 1;" ::: "memory");
        __syncthreads();
        if (s + 2 < S) stage_load((s + 2) % 3, (s + 2) * 32);

        uint32_t ab = sb + (s % 3) * GSTAGE;
        uint32_t bb = ab + GA_BYTES;
        #pragma unroll
        for (int k16 = 0; k16 < 2; k16++) {
            uint32_t af[4][4], bf[NT8 / 2][4];
            #pragma unroll
            for (int mt = 0; mt < 4; mt++) {
                uint32_t addr = ab + (wm * 64 + mt * 16 + (lane & 15)) * GA_ST
                              + k16 * 32 + ((lane >> 4) << 4);
                ldsm4(af[mt], addr);
            }
            #pragma unroll
            for (int bt = 0; bt < NT8 / 2; bt++) {
                uint32_t addr = bb + (k16 * 16 + (lane & 15)) * GB_ST
                              + (wn * (BN / 4) + bt * 16 + ((lane >> 4) << 3)) * 2;
                ldsm4t(bf[bt], addr);
            }
            #pragma unroll
            for (int mt = 0; mt < 4; mt++)
                #pragma unroll
                for (int nt = 0; nt < NT8; nt++)
                    mma_f16(acc[mt][nt], af[mt], &bf[nt >> 1][(nt & 1) * 2]);
        }
    }

    #pragma unroll
    for (int mt = 0; mt < 4; mt++) {
        int r0 = mBase + wm * 64 + mt * 16 + gid;
        #pragma unroll
        for (int nt = 0; nt < NT8; nt++) {
            int cN = nBase + wn * (BN / 4) + nt * 8 + tig * 2;
            float2 bv = *(const float2*)(bias + cN);
            float o0x = acc[mt][nt][0] + bv.x;
            float o0y = acc[mt][nt][1] + bv.y;
            float o1x = acc[mt][nt][2] + bv.x;
            float o1y = acc[mt][nt][3] + bv.y;
            if (EPI) {
                float2 rv0 = *(const float2*)(resid + (size_t)r0 * N + cN);
                float2 rv1 = *(const float2*)(resid + (size_t)(r0 + 8) * N + cN);
                o0x += rv0.x; o0y += rv0.y;
                o1x += rv1.x; o1y += rv1.y;
            }
            if (sizeof(OutT) == 2) {
                *(__half2*)((__half*)Cmat + (size_t)r0 * N + cN)       = __floats2half2_rn(o0x, o0y);
                *(__half2*)((__half*)Cmat + (size_t)(r0 + 8) * N + cN) = __floats2half2_rn(o1x, o1y);
            } else {
                *(float2*)((float*)Cmat + (size_t)r0 * N + cN)       = make_float2(o0x, o0y);
                *(float2*)((float*)Cmat + (size_t)(r0 + 8) * N + cN) = make_float2(o1x, o1y);
            }
        }
    }
}

// ---------------- 3. depthwise causal conv1d + silu (fp16 in/out) ----------------
__global__ void conv_silu_kernel(const float* __restrict__ cw,
                                 const float* __restrict__ cb) {
    int i = blockIdx.x * 256 + threadIdx.x;
    int d   = i & (DI - 1);
    int tok = i >> 11;
    int t   = tok & (T_ - 1);
    float4 w = *(const float4*)(cw + d * 4);
    const __half* base = g_projh + (size_t)tok * (2 * DI) + d;
    float acc = cb[d];
    if (t >= 3) acc = fmaf(w.x, __half2float(base[-3 * 2 * DI]), acc);
    if (t >= 2) acc = fmaf(w.y, __half2float(base[-2 * 2 * DI]), acc);
    if (t >= 1) acc = fmaf(w.z, __half2float(base[-1 * 2 * DI]), acc);
    acc = fmaf(w.w, __half2float(base[0]), acc);
    g_xch[i] = __float2half(siluf_(acc));
}

// ---------------- 4. B_t / C_t: fp16 mma split-K GEMM (M=TOK, N=32, K=DI) ----------------
#define CA_BYTES (128 * 80)
#define CB_BYTES (32 * 80)
#define CSTAGE (CA_BYTES + CB_BYTES)
#define CSM (3 * CSTAGE)

__global__ __launch_bounds__(256) void bc_mma_kernel() {
    extern __shared__ char sm[];
    uint32_t sb = smem_u32(sm);
    int tid = threadIdx.x;
    int wid = tid >> 5, lane = tid & 31;
    int wm = wid >> 1, wn = wid & 1;
    int gid = lane >> 2, tig = lane & 3;
    int tok0 = blockIdx.x * 128;
    int kBase = blockIdx.y * (DI / KSL);
    const __half* X = g_xch;
    const __half* W = g_WBC;

    float acc[2][2][4];
    #pragma unroll
    for (int i = 0; i < 2; i++)
        #pragma unroll
        for (int j = 0; j < 2; j++)
            #pragma unroll
            for (int c = 0; c < 4; c++) acc[i][j][c] = 0.f;

    auto stage_load = [&](int buf, int k0) {
        uint32_t ab = sb + buf * CSTAGE;
        uint32_t bb = ab + CA_BYTES;
        #pragma unroll
        for (int q = 0; q < 2; q++) {
            int lin = tid + q * 256;
            int row = lin >> 2, ch = lin & 3;
            cp16(ab + row * 80 + ch * 16,
                 X + (size_t)(tok0 + row) * DI + kBase + k0 + ch * 8);
        }
        if (tid < 128) {
            int row = tid >> 2, ch = tid & 3;
            cp16(bb + row * 80 + ch * 16,
                 W + (size_t)(kBase + k0 + row) * 32 + ch * 8);
        }
        asm volatile("cp.async.commit_group;" ::: "memory");
    };

    const int S = (DI / KSL) / 32;
    stage_load(0, 0);
    stage_load(1, 32);
    for (int s = 0; s < S; s++) {
        asm volatile("cp.async.wait_group 1;" ::: "memory");
        __syncthreads();
        if (s + 2 < S) stage_load((s + 2) % 3, (s + 2) * 32);

        uint32_t ab = sb + (s % 3) * CSTAGE;
        uint32_t bb = ab + CA_BYTES;
        #pragma unroll
        for (int k16 = 0; k16 < 2; k16++) {
            uint32_t af[2][4], bf[4];
            #pragma unroll
            for (int mt = 0; mt < 2; mt++) {
                uint32_t addr = ab + (wm * 32 + mt * 16 + (lane & 15)) * 80
                              + k16 * 32 + ((lane >> 4) << 4);
                ldsm4(af[mt], addr);
            }
            {
                uint32_t addr = bb + (k16 * 16 + (lane & 15)) * 80
                              + (wn * 16 + ((lane >> 4) << 3)) * 2;
                ldsm4t(bf, addr);
            }
            #pragma unroll
            for (int mt = 0; mt < 2; mt++)
                #pragma unroll
                for (int nt = 0; nt < 2; nt++)
                    mma_f16(acc[mt][nt], af[mt], &bf[nt * 2]);
        }
    }

    #pragma unroll
    for (int mt = 0; mt < 2; mt++) {
        int r0 = tok0 + wm * 32 + mt * 16 + gid;
        #pragma unroll
        for (int nt = 0; nt < 2; nt++) {
            int o = wn * 16 + nt * 8 + tig * 2;
            *(float2*)&g_BCp[blockIdx.y][r0][o]     = make_float2(acc[mt][nt][0], acc[mt][nt][1]);
            *(float2*)&g_BCp[blockIdx.y][r0 + 8][o] = make_float2(acc[mt][nt][2], acc[mt][nt][3]);
        }
    }
}

__global__ void bc_reduce_kernel(const float* __restrict__ bB,
                                 const float* __restrict__ bC) {
    int idx = blockIdx.x * 256 + threadIdx.x;
    int o = idx & 31, tok = idx >> 5;
    float s = 0.f;
    #pragma unroll
    for (int p = 0; p < KSL; p++) s += g_BCp[p][tok][o];
    if (o < 16) g_Bt[tok * DS + o]        = s + bB[o];
    else        g_Ct[tok * DS + (o - 16)] = s + bC[o - 16];
}

// ---------------- 5. scan pass 1 ----------------
__global__ void scan1_kernel(const float* __restrict__ A) {
    __shared__ float sB[CHL][DS];
    int tid = threadIdx.x;
    int d  = blockIdx.x * 128 + tid;
    int ch = blockIdx.y, bb = blockIdx.z;
    int tok0 = bb * T_ + ch * CHL;
    float* sBf = &sB[0][0];
    #pragma unroll
    for (int q = 0; q < (CHL * DS) / 128; q++)
        sBf[tid + q * 128] = g_Bt[tok0 * DS + tid + q * 128];
    float a[DS], h[DS];
    #pragma unroll
    for (int s = 0; s < DS; s++) {
        a[s] = sigmoidf_(A[d * DS + s]);
        h[s] = 0.f;
    }
    __syncthreads();
    for (int t = 0; t < CHL; t++) {
        float x = __half2float(g_xch[(size_t)(tok0 + t) * DI + d]);
        #pragma unroll
        for (int s = 0; s < DS; s++)
            h[s] = fmaf(a[s], h[s], sB[t][s] * x);
    }
    float* ep = g_E + ((size_t)(bb * NCH + ch) * DI + d) * DS;
    #pragma unroll
    for (int s = 0; s < DS; s++) ep[s] = h[s];
}

// ---------------- 6. serial carry across chunks ----------------
__global__ void carry_kernel(const float* __restrict__ A) {
    int idx = blockIdx.x * 256 + threadIdx.x;
    int d = idx & (DI - 1), bb = idx >> 11;
    float aL[DS], st[DS];
    #pragma unroll
    for (int s = 0; s < DS; s++) {
        float a = sigmoidf_(A[d * DS + s]);
        #pragma unroll
        for (int r = 0; r < 5; r++) a *= a;   // a^32 (CHL=32)
        aL[s] = a;
        st[s] = 0.f;
    }
    for (int c = 0; c < NCH; c++) {
        float* sp = g_S + ((size_t)(bb * NCH + c) * DI + d) * DS;
        const float* ep = g_E + ((size_t)(bb * NCH + c) * DI + d) * DS;
        #pragma unroll
        for (int s = 0; s < DS; s++) sp[s] = st[s];
        #pragma unroll
        for (int s = 0; s < DS; s++) st[s] = fmaf(aL[s], st[s], ep[s]);
    }
}

// ---------------- 7. scan pass 2 + gate epilogue ----------------
__global__ void scan2_kernel(const float* __restrict__ A,
                             const float* __restrict__ Dv) {
    __shared__ float sB[CHL][DS], sC[CHL][DS];
    int tid = threadIdx.x;
    int d  = blockIdx.x * 128 + tid;
    int ch = blockIdx.y, bb = blockIdx.z;
    int tok0 = bb * T_ + ch * CHL;
    #pragma unroll
    for (int q = 0; q < (CHL * DS) / 128; q++) {
        (&sB[0][0])[tid + q * 128] = g_Bt[tok0 * DS + tid + q * 128];
        (&sC[0][0])[tid + q * 128] = g_Ct[tok0 * DS + tid + q * 128];
    }
    const float* sp = g_S + ((size_t)(bb * NCH + ch) * DI + d) * DS;
    float a[DS], h[DS];
    #pragma unroll
    for (int s = 0; s < DS; s++) {
        a[s] = sigmoidf_(A[d * DS + s]);
        h[s] = sp[s];
    }
    float Dd = Dv[d];
    __syncthreads();
    for (int t = 0; t < CHL; t++) {
        int tok = tok0 + t;
        float x = __half2float(g_xch[(size_t)tok * DI + d]);
        float yv = Dd * x;
        #pragma unroll
        for (int s = 0; s < DS; s++) {
            h[s] = fmaf(a[s], h[s], sB[t][s] * x);
            yv = fmaf(h[s], sC[t][s], yv);
        }
        float gt = __half2float(g_projh[(size_t)tok * (2 * DI) + DI + d]);
        g_y[(size_t)tok * DI + d] = __float2half(yv * siluf_(gt));
    }
}

// ---------------- launch ----------------
#define GSM_OF(BN) (3 * (GA_BYTES + 32 * (BN * 2 + 16)))

extern "C" void kernel_launch(void* const* d_in, const int* in_sizes, int n_in,
                              void* d_out, int out_size) {
    const float* x      = (const float*)d_in[0];
    const float* ln_g   = (const float*)d_in[1];
    const float* ln_b   = (const float*)d_in[2];
    const float* W_in   = (const float*)d_in[3];
    const float* b_in   = (const float*)d_in[4];
    const float* conv_w = (const float*)d_in[5];
    const float* conv_b = (const float*)d_in[6];
    const float* A      = (const float*)d_in[7];
    const float* W_B    = (const float*)d_in[8];
    const float* b_B    = (const float*)d_in[9];
    const float* W_C    = (const float*)d_in[10];
    const float* b_C    = (const float*)d_in[11];
    const float* Dv     = (const float*)d_in[12];
    const float* W_out  = (const float*)d_in[13];
    const float* b_out  = (const float*)d_in[14];
    float* out = (float*)d_out;

    void *pxnh, *pprojh, *py, *pwih, *pwoh;
    cudaGetSymbolAddress(&pxnh,  g_xnh);
    cudaGetSymbolAddress(&pprojh, g_projh);
    cudaGetSymbolAddress(&py,    g_y);
    cudaGetSymbolAddress(&pwih,  g_WinH);
    cudaGetSymbolAddress(&pwoh,  g_WoutH);

    cudaFuncSetAttribute((const void*)gemm_f16<0, 256, __half>,
                         cudaFuncAttributeMaxDynamicSharedMemorySize, GSM_OF(256));
    cudaFuncSetAttribute((const void*)gemm_f16<1, 128, float>,
                         cudaFuncAttributeMaxDynamicSharedMemorySize, GSM_OF(128));
    cudaFuncSetAttribute((const void*)bc_mma_kernel,
                         cudaFuncAttributeMaxDynamicSharedMemorySize, CSM);

    ln_kernel<<<TOK, 256>>>(x, ln_g, ln_b);
    f2h_kernel<<<(DM * 2 * DI) / 1024, 256>>>(W_in, (__half*)pwih);
    f2h_kernel<<<(DI * DM) / 1024, 256>>>(W_out, (__half*)pwoh);
    pack_wbc_kernel<<<(DI * 32) / 256, 256>>>(W_B, W_C);

    // proj = xn @ W_in + b_in    (M=2048, N=4096, K=1024), 128x256 tiles
    gemm_f16<0, 256, __half><<<dim3((2 * DI) / 256, TOK / 128), 256, GSM_OF(256)>>>(
        (const __half*)pxnh, (const __half*)pwih, b_in, x /*unused*/,
        (__half*)pprojh, TOK, 2 * DI, DM);

    conv_silu_kernel<<<(TOK * DI) / 256, 256>>>(conv_w, conv_b);

    bc_mma_kernel<<<dim3(TOK / 128, KSL), 256, CSM>>>();
    bc_reduce_kernel<<<(TOK * 32) / 256, 256>>>(b_B, b_C);

    scan1_kernel<<<dim3(DI / 128, NCH, B_), 128>>>(A);
    carry_kernel<<<(B_ * DI) / 256, 256>>>(A);
    scan2_kernel<<<dim3(DI / 128, NCH, B_), 128>>>(A, Dv);

    // out = y @ W_out + b_out + x   (M=2048, N=1024, K=2048), 128x128 tiles
    gemm_f16<1, 128, float><<<dim3(DM / 128, TOK / 128), 256, GSM_OF(128)>>>(
        (const __half*)py, (const __half*)pwoh, b_out, x, out, TOK, DM, DI);
}

// round 9
// speedup vs baseline: 3.2789x; 1.0139x over previous
#include <cuda_runtime.h>
#include <cuda_fp16.h>
#include <cstdint>

// ---------------- problem constants ----------------
#define B_   2
#define T_   1024
#define DM   1024      // d_model
#define DI   2048      // d_inner
#define DS   16        // d_state
#define TOK  (B_ * T_) // 2048 tokens
#define NCH  32        // scan chunks
#define CHL  32        // chunk length
#define KSL  8         // bc split-K slices

// ---------------- scratch (static device memory) ----------------
__device__ __half g_xnh  [TOK * DM];        // fp16 LN output (gemm1 A)
__device__ __half g_WinH [DM * 2 * DI];     // fp16 W_in
__device__ __half g_WoutH[DI * DM];         // fp16 W_out
__device__ __half g_WBC  [DI * 32];         // fp16 [W_B | W_C]
__device__ __half g_projh[TOK * 2 * DI];    // in_proj output (xp | gate), fp16
__device__ __half g_xch  [TOK * DI];        // conv+silu output fp16
__device__ float  g_Bt   [TOK * DS];
__device__ float  g_Ct   [TOK * DS];
__device__ float  g_E    [B_ * NCH * DI * DS];
__device__ float  g_S    [B_ * NCH * DI * DS];
__device__ __half g_y    [TOK * DI];        // gated SSM output fp16 (gemm2 A)
__device__ float  g_BCp  [KSL][TOK][32];

__device__ __forceinline__ float sigmoidf_(float x) { return 1.0f / (1.0f + __expf(-x)); }
__device__ __forceinline__ float siluf_(float x)    { return x / (1.0f + __expf(-x)); }

__device__ __forceinline__ uint32_t smem_u32(const void* p) {
    uint32_t a;
    asm("{ .reg .u64 t; cvta.to.shared.u64 t, %1; cvt.u32.u64 %0, t; }"
        : "=r"(a) : "l"(p));
    return a;
}
__device__ __forceinline__ void cp16(uint32_t dst, const void* src) {
    asm volatile("cp.async.cg.shared.global [%0], [%1], 16;"
                 :: "r"(dst), "l"(src) : "memory");
}
__device__ __forceinline__ void ldsm4(uint32_t* r, uint32_t addr) {
    asm volatile("ldmatrix.sync.aligned.m8n8.x4.shared.b16 {%0,%1,%2,%3}, [%4];"
        : "=r"(r[0]), "=r"(r[1]), "=r"(r[2]), "=r"(r[3]) : "r"(addr));
}
__device__ __forceinline__ void ldsm4t(uint32_t* r, uint32_t addr) {
    asm volatile("ldmatrix.sync.aligned.m8n8.x4.trans.shared.b16 {%0,%1,%2,%3}, [%4];"
        : "=r"(r[0]), "=r"(r[1]), "=r"(r[2]), "=r"(r[3]) : "r"(addr));
}
__device__ __forceinline__ void mma_f16(float* c, const uint32_t* a, const uint32_t* b) {
    asm volatile(
        "mma.sync.aligned.m16n8k16.row.col.f32.f16.f16.f32 "
        "{%0,%1,%2,%3}, {%4,%5,%6,%7}, {%8,%9}, {%0,%1,%2,%3};"
        : "+f"(c[0]), "+f"(c[1]), "+f"(c[2]), "+f"(c[3])
        : "r"(a[0]), "r"(a[1]), "r"(a[2]), "r"(a[3]), "r"(b[0]), "r"(b[1]));
}

// ---------------- 1. LayerNorm (writes fp16) ----------------
__global__ void ln_kernel(const float* __restrict__ x,
                          const float* __restrict__ g,
                          const float* __restrict__ b) {
    int row = blockIdx.x;
    int tid = threadIdx.x;
    const float4* xr = (const float4*)(x + (size_t)row * DM);
    float4 v = xr[tid];
    float s = v.x + v.y + v.z + v.w;
    float q = v.x * v.x + v.y * v.y + v.z * v.z + v.w * v.w;
    #pragma unroll
    for (int o = 16; o; o >>= 1) {
        s += __shfl_down_sync(0xFFFFFFFFu, s, o);
        q += __shfl_down_sync(0xFFFFFFFFu, q, o);
    }
    __shared__ float ss[8], sq[8];
    __shared__ float smu, srstd;
    int w = tid >> 5, l = tid & 31;
    if (l == 0) { ss[w] = s; sq[w] = q; }
    __syncthreads();
    if (tid == 0) {
        float S = 0.f, Q = 0.f;
        #pragma unroll
        for (int i = 0; i < 8; i++) { S += ss[i]; Q += sq[i]; }
        float mu = S * (1.0f / DM);
        float var = Q * (1.0f / DM) - mu * mu;
        smu = mu; srstd = rsqrtf(var + 1e-5f);
    }
    __syncthreads();
    float mu = smu, rstd = srstd;
    float4 gv = ((const float4*)g)[tid];
    float4 bv = ((const float4*)b)[tid];
    __half2* orow = (__half2*)(g_xnh + (size_t)row * DM);
    orow[tid * 2]     = __floats2half2_rn((v.x - mu) * rstd * gv.x + bv.x,
                                          (v.y - mu) * rstd * gv.y + bv.y);
    orow[tid * 2 + 1] = __floats2half2_rn((v.z - mu) * rstd * gv.z + bv.z,
                                          (v.w - mu) * rstd * gv.w + bv.w);
}

// ---------------- weight converts ----------------
__global__ void f2h_kernel(const float* __restrict__ src, __half* __restrict__ dst) {
    int i = blockIdx.x * 256 + threadIdx.x;
    float4 v = ((const float4*)src)[i];
    ((__half2*)dst)[i * 2]     = __floats2half2_rn(v.x, v.y);
    ((__half2*)dst)[i * 2 + 1] = __floats2half2_rn(v.z, v.w);
}
__global__ void pack_wbc_kernel(const float* __restrict__ WB,
                                const float* __restrict__ WC) {
    int i = blockIdx.x * 256 + threadIdx.x;   // DI*32
    int k = i >> 5, o = i & 31;
    float v = (o < 16) ? WB[k * DS + o] : WC[k * DS + (o - 16)];
    g_WBC[i] = __float2half(v);
}

// ---------------- fp16 mma GEMM, 512 threads: C = A @ B + bias (+resid) ----------------
// A: MxK fp16 row-major.  B: KxN fp16 row-major.  Block tile 128 x BN, K-step 32.
// Warp grid 4(m) x 4(n): warp tile 32 x BN/4.
#define GA_ST 80                    // A smem row stride bytes (32 fp16 + 8B pad)
#define GA_BYTES (128 * GA_ST)      // 10240

template <int EPI, int BN, typename OutT>
__global__ __launch_bounds__(512) void gemm_f16(
    const __half* __restrict__ Amat, const __half* __restrict__ Bmat,
    const float* __restrict__ bias, const float* __restrict__ resid,
    OutT* __restrict__ Cmat, int M, int N, int K)
{
    constexpr int GB_ST = BN * 2 + 16;            // B smem row stride bytes
    constexpr int GB_BYTES = 32 * GB_ST;
    constexpr int GSTAGE = GA_BYTES + GB_BYTES;
    constexpr int NT8 = BN / 32;                  // n8 sub-tiles per warp

    extern __shared__ char sm[];
    uint32_t sb = smem_u32(sm);
    int tid = threadIdx.x;
    int wid = tid >> 5, lane = tid & 31;
    int wm = wid >> 2, wn = wid & 3;              // 4(m) x 4(n)
    int gid = lane >> 2, tig = lane & 3;
    int mBase = blockIdx.y * 128, nBase = blockIdx.x * BN;
    const int S = K / 32;

    float acc[2][NT8][4];
    #pragma unroll
    for (int i = 0; i < 2; i++)
        #pragma unroll
        for (int j = 0; j < NT8; j++)
            #pragma unroll
            for (int c = 0; c < 4; c++) acc[i][j][c] = 0.f;

    auto stage_load = [&](int buf, int k0) {
        uint32_t ab = sb + buf * GSTAGE;
        uint32_t bb = ab + GA_BYTES;
        {                                              // A: 128 rows x 4 chunks = 512
            int row = tid >> 2, ch = tid & 3;
            cp16(ab + row * GA_ST + ch * 16,
                 Amat + (size_t)(mBase + row) * K + k0 + ch * 8);
        }
        #pragma unroll
        for (int q = 0; q < BN / 128; q++) {           // B: 32 rows x BN/8 chunks
            int lin = tid + q * 512;
            int row = lin / (BN / 8), ch = lin % (BN / 8);
            cp16(bb + row * GB_ST + ch * 16,
                 Bmat + (size_t)(k0 + row) * N + nBase + ch * 8);
        }
        asm volatile("cp.async.commit_group;" ::: "memory");
    };

    stage_load(0, 0);
    stage_load(1, 32);
    for (int s = 0; s < S; s++) {
        asm volatile("cp.async.wait_group 1;" ::: "memory");
        __syncthreads();
        if (s + 2 < S) stage_load((s + 2) % 3, (s + 2) * 32);

        uint32_t ab = sb + (s % 3) * GSTAGE;
        uint32_t bb = ab + GA_BYTES;
        #pragma unroll
        for (int k16 = 0; k16 < 2; k16++) {
            uint32_t af[2][4], bf[NT8 / 2][4];
            #pragma unroll
            for (int mt = 0; mt < 2; mt++) {
                uint32_t addr = ab + (wm * 32 + mt * 16 + (lane & 15)) * GA_ST
                              + k16 * 32 + ((lane >> 4) << 4);
                ldsm4(af[mt], addr);
            }
            #pragma unroll
            for (int bt = 0; bt < NT8 / 2; bt++) {
                uint32_t addr = bb + (k16 * 16 + (lane & 15)) * GB_ST
                              + (wn * (BN / 4) + bt * 16 + ((lane >> 4) << 3)) * 2;
                ldsm4t(bf[bt], addr);
            }
            #pragma unroll
            for (int mt = 0; mt < 2; mt++)
                #pragma unroll
                for (int nt = 0; nt < NT8; nt++)
                    mma_f16(acc[mt][nt], af[mt], &bf[nt >> 1][(nt & 1) * 2]);
        }
    }

    #pragma unroll
    for (int mt = 0; mt < 2; mt++) {
        int r0 = mBase + wm * 32 + mt * 16 + gid;
        #pragma unroll
        for (int nt = 0; nt < NT8; nt++) {
            int cN = nBase + wn * (BN / 4) + nt * 8 + tig * 2;
            float2 bv = *(const float2*)(bias + cN);
            float o0x = acc[mt][nt][0] + bv.x;
            float o0y = acc[mt][nt][1] + bv.y;
            float o1x = acc[mt][nt][2] + bv.x;
            float o1y = acc[mt][nt][3] + bv.y;
            if (EPI) {
                float2 rv0 = *(const float2*)(resid + (size_t)r0 * N + cN);
                float2 rv1 = *(const float2*)(resid + (size_t)(r0 + 8) * N + cN);
                o0x += rv0.x; o0y += rv0.y;
                o1x += rv1.x; o1y += rv1.y;
            }
            if (sizeof(OutT) == 2) {
                *(__half2*)((__half*)Cmat + (size_t)r0 * N + cN)       = __floats2half2_rn(o0x, o0y);
                *(__half2*)((__half*)Cmat + (size_t)(r0 + 8) * N + cN) = __floats2half2_rn(o1x, o1y);
            } else {
                *(float2*)((float*)Cmat + (size_t)r0 * N + cN)       = make_float2(o0x, o0y);
                *(float2*)((float*)Cmat + (size_t)(r0 + 8) * N + cN) = make_float2(o1x, o1y);
            }
        }
    }
}

// ---------------- 3. depthwise causal conv1d + silu (fp16 in/out) ----------------
__global__ void conv_silu_kernel(const float* __restrict__ cw,
                                 const float* __restrict__ cb) {
    int i = blockIdx.x * 256 + threadIdx.x;
    int d   = i & (DI - 1);
    int tok = i >> 11;
    int t   = tok & (T_ - 1);
    float4 w = *(const float4*)(cw + d * 4);
    const __half* base = g_projh + (size_t)tok * (2 * DI) + d;
    float acc = cb[d];
    if (t >= 3) acc = fmaf(w.x, __half2float(base[-3 * 2 * DI]), acc);
    if (t >= 2) acc = fmaf(w.y, __half2float(base[-2 * 2 * DI]), acc);
    if (t >= 1) acc = fmaf(w.z, __half2float(base[-1 * 2 * DI]), acc);
    acc = fmaf(w.w, __half2float(base[0]), acc);
    g_xch[i] = __float2half(siluf_(acc));
}

// ---------------- 4. B_t / C_t: fp16 mma split-K GEMM (M=TOK, N=32, K=DI) ----------------
#define CA_BYTES (128 * 80)
#define CB_BYTES (32 * 80)
#define CSTAGE (CA_BYTES + CB_BYTES)
#define CSM (3 * CSTAGE)

__global__ __launch_bounds__(256) void bc_mma_kernel() {
    extern __shared__ char sm[];
    uint32_t sb = smem_u32(sm);
    int tid = threadIdx.x;
    int wid = tid >> 5, lane = tid & 31;
    int wm = wid >> 1, wn = wid & 1;
    int gid = lane >> 2, tig = lane & 3;
    int tok0 = blockIdx.x * 128;
    int kBase = blockIdx.y * (DI / KSL);
    const __half* X = g_xch;
    const __half* W = g_WBC;

    float acc[2][2][4];
    #pragma unroll
    for (int i = 0; i < 2; i++)
        #pragma unroll
        for (int j = 0; j < 2; j++)
            #pragma unroll
            for (int c = 0; c < 4; c++) acc[i][j][c] = 0.f;

    auto stage_load = [&](int buf, int k0) {
        uint32_t ab = sb + buf * CSTAGE;
        uint32_t bb = ab + CA_BYTES;
        #pragma unroll
        for (int q = 0; q < 2; q++) {
            int lin = tid + q * 256;
            int row = lin >> 2, ch = lin & 3;
            cp16(ab + row * 80 + ch * 16,
                 X + (size_t)(tok0 + row) * DI + kBase + k0 + ch * 8);
        }
        if (tid < 128) {
            int row = tid >> 2, ch = tid & 3;
            cp16(bb + row * 80 + ch * 16,
                 W + (size_t)(kBase + k0 + row) * 32 + ch * 8);
        }
        asm volatile("cp.async.commit_group;" ::: "memory");
    };

    const int S = (DI / KSL) / 32;
    stage_load(0, 0);
    stage_load(1, 32);
    for (int s = 0; s < S; s++) {
        asm volatile("cp.async.wait_group 1;" ::: "memory");
        __syncthreads();
        if (s + 2 < S) stage_load((s + 2) % 3, (s + 2) * 32);

        uint32_t ab = sb + (s % 3) * CSTAGE;
        uint32_t bb = ab + CA_BYTES;
        #pragma unroll
        for (int k16 = 0; k16 < 2; k16++) {
            uint32_t af[2][4], bf[4];
            #pragma unroll
            for (int mt = 0; mt < 2; mt++) {
                uint32_t addr = ab + (wm * 32 + mt * 16 + (lane & 15)) * 80
                              + k16 * 32 + ((lane >> 4) << 4);
                ldsm4(af[mt], addr);
            }
            {
                uint32_t addr = bb + (k16 * 16 + (lane & 15)) * 80
                              + (wn * 16 + ((lane >> 4) << 3)) * 2;
                ldsm4t(bf, addr);
            }
            #pragma unroll
            for (int mt = 0; mt < 2; mt++)
                #pragma unroll
                for (int nt = 0; nt < 2; nt++)
                    mma_f16(acc[mt][nt], af[mt], &bf[nt * 2]);
        }
    }

    #pragma unroll
    for (int mt = 0; mt < 2; mt++) {
        int r0 = tok0 + wm * 32 + mt * 16 + gid;
        #pragma unroll
        for (int nt = 0; nt < 2; nt++) {
            int o = wn * 16 + nt * 8 + tig * 2;
            *(float2*)&g_BCp[blockIdx.y][r0][o]     = make_float2(acc[mt][nt][0], acc[mt][nt][1]);
            *(float2*)&g_BCp[blockIdx.y][r0 + 8][o] = make_float2(acc[mt][nt][2], acc[mt][nt][3]);
        }
    }
}

__global__ void bc_reduce_kernel(const float* __restrict__ bB,
                                 const float* __restrict__ bC) {
    int idx = blockIdx.x * 256 + threadIdx.x;
    int o = idx & 31, tok = idx >> 5;
    float s = 0.f;
    #pragma unroll
    for (int p = 0; p < KSL; p++) s += g_BCp[p][tok][o];
    if (o < 16) g_Bt[tok * DS + o]        = s + bB[o];
    else        g_Ct[tok * DS + (o - 16)] = s + bC[o - 16];
}

// ---------------- 5. scan pass 1 ----------------
__global__ void scan1_kernel(const float* __restrict__ A) {
    __shared__ float sB[CHL][DS];
    int tid = threadIdx.x;
    int d  = blockIdx.x * 128 + tid;
    int ch = blockIdx.y, bb = blockIdx.z;
    int tok0 = bb * T_ + ch * CHL;
    float* sBf = &sB[0][0];
    #pragma unroll
    for (int q = 0; q < (CHL * DS) / 128; q++)
        sBf[tid + q * 128] = g_Bt[tok0 * DS + tid + q * 128];
    float a[DS], h[DS];
    #pragma unroll
    for (int s = 0; s < DS; s++) {
        a[s] = sigmoidf_(A[d * DS + s]);
        h[s] = 0.f;
    }
    __syncthreads();
    for (int t = 0; t < CHL; t++) {
        float x = __half2float(g_xch[(size_t)(tok0 + t) * DI + d]);
        #pragma unroll
        for (int s = 0; s < DS; s++)
            h[s] = fmaf(a[s], h[s], sB[t][s] * x);
    }
    float* ep = g_E + ((size_t)(bb * NCH + ch) * DI + d) * DS;
    #pragma unroll
    for (int s = 0; s < DS; s++) ep[s] = h[s];
}

// ---------------- 6. serial carry across chunks ----------------
__global__ void carry_kernel(const float* __restrict__ A) {
    int idx = blockIdx.x * 256 + threadIdx.x;
    int d = idx & (DI - 1), bb = idx >> 11;
    float aL[DS], st[DS];
    #pragma unroll
    for (int s = 0; s < DS; s++) {
        float a = sigmoidf_(A[d * DS + s]);
        #pragma unroll
        for (int r = 0; r < 5; r++) a *= a;   // a^32 (CHL=32)
        aL[s] = a;
        st[s] = 0.f;
    }
    for (int c = 0; c < NCH; c++) {
        float* sp = g_S + ((size_t)(bb * NCH + c) * DI + d) * DS;
        const float* ep = g_E + ((size_t)(bb * NCH + c) * DI + d) * DS;
        #pragma unroll
        for (int s = 0; s < DS; s++) sp[s] = st[s];
        #pragma unroll
        for (int s = 0; s < DS; s++) st[s] = fmaf(aL[s], st[s], ep[s]);
    }
}

// ---------------- 7. scan pass 2 + gate epilogue ----------------
__global__ void scan2_kernel(const float* __restrict__ A,
                             const float* __restrict__ Dv) {
    __shared__ float sB[CHL][DS], sC[CHL][DS];
    int tid = threadIdx.x;
    int d  = blockIdx.x * 128 + tid;
    int ch = blockIdx.y, bb = blockIdx.z;
    int tok0 = bb * T_ + ch * CHL;
    #pragma unroll
    for (int q = 0; q < (CHL * DS) / 128; q++) {
        (&sB[0][0])[tid + q * 128] = g_Bt[tok0 * DS + tid + q * 128];
        (&sC[0][0])[tid + q * 128] = g_Ct[tok0 * DS + tid + q * 128];
    }
    const float* sp = g_S + ((size_t)(bb * NCH + ch) * DI + d) * DS;
    float a[DS], h[DS];
    #pragma unroll
    for (int s = 0; s < DS; s++) {
        a[s] = sigmoidf_(A[d * DS + s]);
        h[s] = sp[s];
    }
    float Dd = Dv[d];
    __syncthreads();
    for (int t = 0; t < CHL; t++) {
        int tok = tok0 + t;
        float x = __half2float(g_xch[(size_t)tok * DI + d]);
        float yv = Dd * x;
        #pragma unroll
        for (int s = 0; s < DS; s++) {
            h[s] = fmaf(a[s], h[s], sB[t][s] * x);
            yv = fmaf(h[s], sC[t][s], yv);
        }
        float gt = __half2float(g_projh[(size_t)tok * (2 * DI) + DI + d]);
        g_y[(size_t)tok * DI + d] = __float2half(yv * siluf_(gt));
    }
}

// ---------------- launch ----------------
#define GSM_OF(BN) (3 * (GA_BYTES + 32 * (BN * 2 + 16)))

extern "C" void kernel_launch(void* const* d_in, const int* in_sizes, int n_in,
                              void* d_out, int out_size) {
    const float* x      = (const float*)d_in[0];
    const float* ln_g   = (const float*)d_in[1];
    const float* ln_b   = (const float*)d_in[2];
    const float* W_in   = (const float*)d_in[3];
    const float* b_in   = (const float*)d_in[4];
    const float* conv_w = (const float*)d_in[5];
    const float* conv_b = (const float*)d_in[6];
    const float* A      = (const float*)d_in[7];
    const float* W_B    = (const float*)d_in[8];
    const float* b_B    = (const float*)d_in[9];
    const float* W_C    = (const float*)d_in[10];
    const float* b_C    = (const float*)d_in[11];
    const float* Dv     = (const float*)d_in[12];
    const float* W_out  = (const float*)d_in[13];
    const float* b_out  = (const float*)d_in[14];
    float* out = (float*)d_out;

    void *pxnh, *pprojh, *py, *pwih, *pwoh;
    cudaGetSymbolAddress(&pxnh,  g_xnh);
    cudaGetSymbolAddress(&pprojh, g_projh);
    cudaGetSymbolAddress(&py,    g_y);
    cudaGetSymbolAddress(&pwih,  g_WinH);
    cudaGetSymbolAddress(&pwoh,  g_WoutH);

    cudaFuncSetAttribute((const void*)gemm_f16<0, 256, __half>,
                         cudaFuncAttributeMaxDynamicSharedMemorySize, GSM_OF(256));
    cudaFuncSetAttribute((const void*)gemm_f16<1, 128, float>,
                         cudaFuncAttributeMaxDynamicSharedMemorySize, GSM_OF(128));
    cudaFuncSetAttribute((const void*)bc_mma_kernel,
                         cudaFuncAttributeMaxDynamicSharedMemorySize, CSM);

    // launch order chosen so gemm1 is the 4th kernel (ncu -s 5 -c 1 captures it)
    ln_kernel<<<TOK, 256>>>(x, ln_g, ln_b);
    f2h_kernel<<<(DM * 2 * DI) / 1024, 256>>>(W_in, (__half*)pwih);
    f2h_kernel<<<(DI * DM) / 1024, 256>>>(W_out, (__half*)pwoh);

    // proj = xn @ W_in + b_in    (M=2048, N=4096, K=1024), 128x256 tiles, 512 thr
    gemm_f16<0, 256, __half><<<dim3((2 * DI) / 256, TOK / 128), 512, GSM_OF(256)>>>(
        (const __half*)pxnh, (const __half*)pwih, b_in, x /*unused*/,
        (__half*)pprojh, TOK, 2 * DI, DM);

    conv_silu_kernel<<<(TOK * DI) / 256, 256>>>(conv_w, conv_b);

    pack_wbc_kernel<<<(DI * 32) / 256, 256>>>(W_B, W_C);
    bc_mma_kernel<<<dim3(TOK / 128, KSL), 256, CSM>>>();
    bc_reduce_kernel<<<(TOK * 32) / 256, 256>>>(b_B, b_C);

    scan1_kernel<<<dim3(DI / 128, NCH, B_), 128>>>(A);
    carry_kernel<<<(B_ * DI) / 256, 256>>>(A);
    scan2_kernel<<<dim3(DI / 128, NCH, B_), 128>>>(A, Dv);

    // out = y @ W_out + b_out + x   (M=2048, N=1024, K=2048), 128x128 tiles, 512 thr
    gemm_f16<1, 128, float><<<dim3(DM / 128, TOK / 128), 512, GSM_OF(128)>>>(
        (const __half*)py, (const __half*)pwoh, b_out, x, out, TOK, DM, DI);
}

// round 10
// speedup vs baseline: 3.3536x; 1.0228x over previous
#include <cuda_runtime.h>
#include <cuda_fp16.h>
#include <cstdint>

// ---------------- problem constants ----------------
#define B_   2
#define T_   1024
#define DM   1024      // d_model
#define DI   2048      // d_inner
#define DS   16        // d_state
#define TOK  (B_ * T_) // 2048 tokens
#define NCH  32        // scan chunks
#define CHL  32        // chunk length
#define KSL  8         // bc split-K slices

// ---------------- scratch (static device memory) ----------------
__device__ __half g_xnh  [TOK * DM];        // fp16 LN output (gemm1 A)
__device__ __half g_WinH [DM * 2 * DI];     // fp16 W_in
__device__ __half g_WoutH[DI * DM];         // fp16 W_out
__device__ __half g_WBC  [DI * 32];         // fp16 [W_B | W_C]
__device__ __half g_projh[TOK * 2 * DI];    // in_proj output (xp | gate), fp16
__device__ __half g_xch  [TOK * DI];        // conv+silu output fp16
__device__ float  g_Bt   [TOK * DS];
__device__ float  g_Ct   [TOK * DS];
__device__ float  g_E    [B_ * NCH * DI * DS];
__device__ float  g_S    [B_ * NCH * DI * DS];
__device__ __half g_y    [TOK * DI];        // gated SSM output fp16 (gemm2 A)
__device__ float  g_BCp  [KSL][TOK][32];

__device__ __forceinline__ float sigmoidf_(float x) { return 1.0f / (1.0f + __expf(-x)); }
__device__ __forceinline__ float siluf_(float x)    { return x / (1.0f + __expf(-x)); }

__device__ __forceinline__ uint32_t smem_u32(const void* p) {
    uint32_t a;
    asm("{ .reg .u64 t; cvta.to.shared.u64 t, %1; cvt.u32.u64 %0, t; }"
        : "=r"(a) : "l"(p));
    return a;
}
__device__ __forceinline__ void cp16(uint32_t dst, const void* src) {
    asm volatile("cp.async.cg.shared.global [%0], [%1], 16;"
                 :: "r"(dst), "l"(src) : "memory");
}
__device__ __forceinline__ void ldsm4(uint32_t* r, uint32_t addr) {
    asm volatile("ldmatrix.sync.aligned.m8n8.x4.shared.b16 {%0,%1,%2,%3}, [%4];"
        : "=r"(r[0]), "=r"(r[1]), "=r"(r[2]), "=r"(r[3]) : "r"(addr));
}
__device__ __forceinline__ void ldsm4t(uint32_t* r, uint32_t addr) {
    asm volatile("ldmatrix.sync.aligned.m8n8.x4.trans.shared.b16 {%0,%1,%2,%3}, [%4];"
        : "=r"(r[0]), "=r"(r[1]), "=r"(r[2]), "=r"(r[3]) : "r"(addr));
}
__device__ __forceinline__ void mma_f16(float* c, const uint32_t* a, const uint32_t* b) {
    asm volatile(
        "mma.sync.aligned.m16n8k16.row.col.f32.f16.f16.f32 "
        "{%0,%1,%2,%3}, {%4,%5,%6,%7}, {%8,%9}, {%0,%1,%2,%3};"
        : "+f"(c[0]), "+f"(c[1]), "+f"(c[2]), "+f"(c[3])
        : "r"(a[0]), "r"(a[1]), "r"(a[2]), "r"(a[3]), "r"(b[0]), "r"(b[1]));
}

// ---------------- 1. fused prep: f2h(W_in) | f2h(W_out) | pack_wbc | LayerNorm ----------------
#define PREP_WIN_BLKS  ((DM * 2 * DI) / 1024)   // 4096
#define PREP_WOUT_BLKS ((DI * DM) / 1024)       // 2048
#define PREP_WBC_BLKS  ((DI * 32) / 256)        // 256
#define PREP_LN_BLKS   TOK                      // 2048
#define PREP_BLKS (PREP_WIN_BLKS + PREP_WOUT_BLKS + PREP_WBC_BLKS + PREP_LN_BLKS)

__global__ void prep_kernel(const float* __restrict__ x,
                            const float* __restrict__ ln_g,
                            const float* __restrict__ ln_b,
                            const float* __restrict__ W_in,
                            const float* __restrict__ W_out,
                            const float* __restrict__ WB,
                            const float* __restrict__ WC) {
    __shared__ float ss[8], sq[8];
    __shared__ float smu, srstd;
    int blk = blockIdx.x;
    int tid = threadIdx.x;

    if (blk < PREP_WIN_BLKS) {                      // f2h W_in
        int i = blk * 256 + tid;
        float4 v = ((const float4*)W_in)[i];
        ((__half2*)g_WinH)[i * 2]     = __floats2half2_rn(v.x, v.y);
        ((__half2*)g_WinH)[i * 2 + 1] = __floats2half2_rn(v.z, v.w);
        return;
    }
    blk -= PREP_WIN_BLKS;
    if (blk < PREP_WOUT_BLKS) {                     // f2h W_out
        int i = blk * 256 + tid;
        float4 v = ((const float4*)W_out)[i];
        ((__half2*)g_WoutH)[i * 2]     = __floats2half2_rn(v.x, v.y);
        ((__half2*)g_WoutH)[i * 2 + 1] = __floats2half2_rn(v.z, v.w);
        return;
    }
    blk -= PREP_WOUT_BLKS;
    if (blk < PREP_WBC_BLKS) {                      // pack [W_B | W_C]
        int i = blk * 256 + tid;
        int k = i >> 5, o = i & 31;
        float v = (o < 16) ? WB[k * DS + o] : WC[k * DS + (o - 16)];
        g_WBC[i] = __float2half(v);
        return;
    }
    blk -= PREP_WBC_BLKS;
    {                                               // LayerNorm row
        int row = blk;
        const float4* xr = (const float4*)(x + (size_t)row * DM);
        float4 v = xr[tid];
        float s = v.x + v.y + v.z + v.w;
        float q = v.x * v.x + v.y * v.y + v.z * v.z + v.w * v.w;
        #pragma unroll
        for (int o = 16; o; o >>= 1) {
            s += __shfl_down_sync(0xFFFFFFFFu, s, o);
            q += __shfl_down_sync(0xFFFFFFFFu, q, o);
        }
        int w = tid >> 5, l = tid & 31;
        if (l == 0) { ss[w] = s; sq[w] = q; }
        __syncthreads();
        if (tid == 0) {
            float S = 0.f, Q = 0.f;
            #pragma unroll
            for (int i = 0; i < 8; i++) { S += ss[i]; Q += sq[i]; }
            float mu = S * (1.0f / DM);
            float var = Q * (1.0f / DM) - mu * mu;
            smu = mu; srstd = rsqrtf(var + 1e-5f);
        }
        __syncthreads();
        float mu = smu, rstd = srstd;
        float4 gv = ((const float4*)ln_g)[tid];
        float4 bv = ((const float4*)ln_b)[tid];
        __half2* orow = (__half2*)(g_xnh + (size_t)row * DM);
        orow[tid * 2]     = __floats2half2_rn((v.x - mu) * rstd * gv.x + bv.x,
                                              (v.y - mu) * rstd * gv.y + bv.y);
        orow[tid * 2 + 1] = __floats2half2_rn((v.z - mu) * rstd * gv.z + bv.z,
                                              (v.w - mu) * rstd * gv.w + bv.w);
    }
}

// ---------------- fp16 mma GEMM, 256 threads, 2 CTAs/SM: C = A @ B + bias (+resid) ----------------
// A: MxK fp16 row-major.  B: KxN fp16 row-major.  Block tile 128 x 128, K-step 32.
// Warp grid 2(m) x 4(n): warp tile 64 x 32.
#define GA_ST 80                    // A smem row stride bytes (32 fp16 + 8B pad)
#define GA_BYTES (128 * GA_ST)      // 10240
#define GB_ST 272                   // B smem row stride bytes (128 fp16 + 16B pad)
#define GB_BYTES (32 * GB_ST)       // 8704
#define GSTAGE (GA_BYTES + GB_BYTES)
#define GSM (3 * GSTAGE)            // 56832

template <int EPI, typename OutT>
__global__ __launch_bounds__(256, 2) void gemm_f16(
    const __half* __restrict__ Amat, const __half* __restrict__ Bmat,
    const float* __restrict__ bias, const float* __restrict__ resid,
    OutT* __restrict__ Cmat, int M, int N, int K)
{
    extern __shared__ char sm[];
    uint32_t sb = smem_u32(sm);
    int tid = threadIdx.x;
    int wid = tid >> 5, lane = tid & 31;
    int wm = wid >> 2, wn = wid & 3;
    int gid = lane >> 2, tig = lane & 3;
    int mBase = blockIdx.y * 128, nBase = blockIdx.x * 128;
    const int S = K / 32;

    float acc[4][4][4];
    #pragma unroll
    for (int i = 0; i < 4; i++)
        #pragma unroll
        for (int j = 0; j < 4; j++)
            #pragma unroll
            for (int c = 0; c < 4; c++) acc[i][j][c] = 0.f;

    auto stage_load = [&](int buf, int k0) {
        uint32_t ab = sb + buf * GSTAGE;
        uint32_t bb = ab + GA_BYTES;
        #pragma unroll
        for (int q = 0; q < 2; q++) {                 // A: 128 rows x 4 chunks
            int lin = tid + q * 256;
            int row = lin >> 2, ch = lin & 3;
            cp16(ab + row * GA_ST + ch * 16,
                 Amat + (size_t)(mBase + row) * K + k0 + ch * 8);
        }
        #pragma unroll
        for (int q = 0; q < 2; q++) {                 // B: 32 rows x 16 chunks
            int lin = tid + q * 256;
            int row = lin >> 4, ch = lin & 15;
            cp16(bb + row * GB_ST + ch * 16,
                 Bmat + (size_t)(k0 + row) * N + nBase + ch * 8);
        }
        asm volatile("cp.async.commit_group;" ::: "memory");
    };

    stage_load(0, 0);
    stage_load(1, 32);
    for (int s = 0; s < S; s++) {
        asm volatile("cp.async.wait_group 1;" ::: "memory");
        __syncthreads();
        if (s + 2 < S) stage_load((s + 2) % 3, (s + 2) * 32);

        uint32_t ab = sb + (s % 3) * GSTAGE;
        uint32_t bb = ab + GA_BYTES;
        #pragma unroll
        for (int k16 = 0; k16 < 2; k16++) {
            uint32_t af[4][4], bf[2][4];
            #pragma unroll
            for (int mt = 0; mt < 4; mt++) {
                uint32_t addr = ab + (wm * 64 + mt * 16 + (lane & 15)) * GA_ST
                              + k16 * 32 + ((lane >> 4) << 4);
                ldsm4(af[mt], addr);
            }
            #pragma unroll
            for (int bt = 0; bt < 2; bt++) {
                uint32_t addr = bb + (k16 * 16 + (lane & 15)) * GB_ST
                              + (wn * 32 + bt * 16 + ((lane >> 4) << 3)) * 2;
                ldsm4t(bf[bt], addr);
            }
            #pragma unroll
            for (int mt = 0; mt < 4; mt++)
                #pragma unroll
                for (int nt = 0; nt < 4; nt++)
                    mma_f16(acc[mt][nt], af[mt], &bf[nt >> 1][(nt & 1) * 2]);
        }
    }

    #pragma unroll
    for (int mt = 0; mt < 4; mt++) {
        int r0 = mBase + wm * 64 + mt * 16 + gid;
        #pragma unroll
        for (int nt = 0; nt < 4; nt++) {
            int cN = nBase + wn * 32 + nt * 8 + tig * 2;
            float2 bv = *(const float2*)(bias + cN);
            float o0x = acc[mt][nt][0] + bv.x;
            float o0y = acc[mt][nt][1] + bv.y;
            float o1x = acc[mt][nt][2] + bv.x;
            float o1y = acc[mt][nt][3] + bv.y;
            if (EPI) {
                float2 rv0 = *(const float2*)(resid + (size_t)r0 * N + cN);
                float2 rv1 = *(const float2*)(resid + (size_t)(r0 + 8) * N + cN);
                o0x += rv0.x; o0y += rv0.y;
                o1x += rv1.x; o1y += rv1.y;
            }
            if (sizeof(OutT) == 2) {
                *(__half2*)((__half*)Cmat + (size_t)r0 * N + cN)       = __floats2half2_rn(o0x, o0y);
                *(__half2*)((__half*)Cmat + (size_t)(r0 + 8) * N + cN) = __floats2half2_rn(o1x, o1y);
            } else {
                *(float2*)((float*)Cmat + (size_t)r0 * N + cN)       = make_float2(o0x, o0y);
                *(float2*)((float*)Cmat + (size_t)(r0 + 8) * N + cN) = make_float2(o1x, o1y);
            }
        }
    }
}

// ---------------- 3. depthwise causal conv1d + silu (fp16 in/out) ----------------
__global__ void conv_silu_kernel(const float* __restrict__ cw,
                                 const float* __restrict__ cb) {
    int i = blockIdx.x * 256 + threadIdx.x;
    int d   = i & (DI - 1);
    int tok = i >> 11;
    int t   = tok & (T_ - 1);
    float4 w = *(const float4*)(cw + d * 4);
    const __half* base = g_projh + (size_t)tok * (2 * DI) + d;
    float acc = cb[d];
    if (t >= 3) acc = fmaf(w.x, __half2float(base[-3 * 2 * DI]), acc);
    if (t >= 2) acc = fmaf(w.y, __half2float(base[-2 * 2 * DI]), acc);
    if (t >= 1) acc = fmaf(w.z, __half2float(base[-1 * 2 * DI]), acc);
    acc = fmaf(w.w, __half2float(base[0]), acc);
    g_xch[i] = __float2half(siluf_(acc));
}

// ---------------- 4. B_t / C_t: fp16 mma split-K GEMM (M=TOK, N=32, K=DI) ----------------
#define CA_BYTES (128 * 80)
#define CB_BYTES (32 * 80)
#define CSTAGE (CA_BYTES + CB_BYTES)
#define CSM (3 * CSTAGE)

__global__ __launch_bounds__(256) void bc_mma_kernel() {
    extern __shared__ char sm[];
    uint32_t sb = smem_u32(sm);
    int tid = threadIdx.x;
    int wid = tid >> 5, lane = tid & 31;
    int wm = wid >> 1, wn = wid & 1;
    int gid = lane >> 2, tig = lane & 3;
    int tok0 = blockIdx.x * 128;
    int kBase = blockIdx.y * (DI / KSL);
    const __half* X = g_xch;
    const __half* W = g_WBC;

    float acc[2][2][4];
    #pragma unroll
    for (int i = 0; i < 2; i++)
        #pragma unroll
        for (int j = 0; j < 2; j++)
            #pragma unroll
            for (int c = 0; c < 4; c++) acc[i][j][c] = 0.f;

    auto stage_load = [&](int buf, int k0) {
        uint32_t ab = sb + buf * CSTAGE;
        uint32_t bb = ab + CA_BYTES;
        #pragma unroll
        for (int q = 0; q < 2; q++) {
            int lin = tid + q * 256;
            int row = lin >> 2, ch = lin & 3;
            cp16(ab + row * 80 + ch * 16,
                 X + (size_t)(tok0 + row) * DI + kBase + k0 + ch * 8);
        }
        if (tid < 128) {
            int row = tid >> 2, ch = tid & 3;
            cp16(bb + row * 80 + ch * 16,
                 W + (size_t)(kBase + k0 + row) * 32 + ch * 8);
        }
        asm volatile("cp.async.commit_group;" ::: "memory");
    };

    const int S = (DI / KSL) / 32;
    stage_load(0, 0);
    stage_load(1, 32);
    for (int s = 0; s < S; s++) {
        asm volatile("cp.async.wait_group 1;" ::: "memory");
        __syncthreads();
        if (s + 2 < S) stage_load((s + 2) % 3, (s + 2) * 32);

        uint32_t ab = sb + (s % 3) * CSTAGE;
        uint32_t bb = ab + CA_BYTES;
        #pragma unroll
        for (int k16 = 0; k16 < 2; k16++) {
            uint32_t af[2][4], bf[4];
            #pragma unroll
            for (int mt = 0; mt < 2; mt++) {
                uint32_t addr = ab + (wm * 32 + mt * 16 + (lane & 15)) * 80
                              + k16 * 32 + ((lane >> 4) << 4);
                ldsm4(af[mt], addr);
            }
            {
                uint32_t addr = bb + (k16 * 16 + (lane & 15)) * 80
                              + (wn * 16 + ((lane >> 4) << 3)) * 2;
                ldsm4t(bf, addr);
            }
            #pragma unroll
            for (int mt = 0; mt < 2; mt++)
                #pragma unroll
                for (int nt = 0; nt < 2; nt++)
                    mma_f16(acc[mt][nt], af[mt], &bf[nt * 2]);
        }
    }

    #pragma unroll
    for (int mt = 0; mt < 2; mt++) {
        int r0 = tok0 + wm * 32 + mt * 16 + gid;
        #pragma unroll
        for (int nt = 0; nt < 2; nt++) {
            int o = wn * 16 + nt * 8 + tig * 2;
            *(float2*)&g_BCp[blockIdx.y][r0][o]     = make_float2(acc[mt][nt][0], acc[mt][nt][1]);
            *(float2*)&g_BCp[blockIdx.y][r0 + 8][o] = make_float2(acc[mt][nt][2], acc[mt][nt][3]);
        }
    }
}

__global__ void bc_reduce_kernel(const float* __restrict__ bB,
                                 const float* __restrict__ bC) {
    int idx = blockIdx.x * 256 + threadIdx.x;
    int o = idx & 31, tok = idx >> 5;
    float s = 0.f;
    #pragma unroll
    for (int p = 0; p < KSL; p++) s += g_BCp[p][tok][o];
    if (o < 16) g_Bt[tok * DS + o]        = s + bB[o];
    else        g_Ct[tok * DS + (o - 16)] = s + bC[o - 16];
}

// ---------------- 5. scan pass 1 ----------------
__global__ void scan1_kernel(const float* __restrict__ A) {
    __shared__ float sB[CHL][DS];
    int tid = threadIdx.x;
    int d  = blockIdx.x * 128 + tid;
    int ch = blockIdx.y, bb = blockIdx.z;
    int tok0 = bb * T_ + ch * CHL;
    float* sBf = &sB[0][0];
    #pragma unroll
    for (int q = 0; q < (CHL * DS) / 128; q++)
        sBf[tid + q * 128] = g_Bt[tok0 * DS + tid + q * 128];
    float a[DS], h[DS];
    #pragma unroll
    for (int s = 0; s < DS; s++) {
        a[s] = sigmoidf_(A[d * DS + s]);
        h[s] = 0.f;
    }
    __syncthreads();
    for (int t = 0; t < CHL; t++) {
        float x = __half2float(g_xch[(size_t)(tok0 + t) * DI + d]);
        #pragma unroll
        for (int s = 0; s < DS; s++)
            h[s] = fmaf(a[s], h[s], sB[t][s] * x);
    }
    float* ep = g_E + ((size_t)(bb * NCH + ch) * DI + d) * DS;
    #pragma unroll
    for (int s = 0; s < DS; s++) ep[s] = h[s];
}

// ---------------- 6. serial carry across chunks ----------------
__global__ void carry_kernel(const float* __restrict__ A) {
    int idx = blockIdx.x * 256 + threadIdx.x;
    int d = idx & (DI - 1), bb = idx >> 11;
    float aL[DS], st[DS];
    #pragma unroll
    for (int s = 0; s < DS; s++) {
        float a = sigmoidf_(A[d * DS + s]);
        #pragma unroll
        for (int r = 0; r < 5; r++) a *= a;   // a^32 (CHL=32)
        aL[s] = a;
        st[s] = 0.f;
    }
    for (int c = 0; c < NCH; c++) {
        float* sp = g_S + ((size_t)(bb * NCH + c) * DI + d) * DS;
        const float* ep = g_E + ((size_t)(bb * NCH + c) * DI + d) * DS;
        #pragma unroll
        for (int s = 0; s < DS; s++) sp[s] = st[s];
        #pragma unroll
        for (int s = 0; s < DS; s++) st[s] = fmaf(aL[s], st[s], ep[s]);
    }
}

// ---------------- 7. scan pass 2 + gate epilogue ----------------
__global__ void scan2_kernel(const float* __restrict__ A,
                             const float* __restrict__ Dv) {
    __shared__ float sB[CHL][DS], sC[CHL][DS];
    int tid = threadIdx.x;
    int d  = blockIdx.x * 128 + tid;
    int ch = blockIdx.y, bb = blockIdx.z;
    int tok0 = bb * T_ + ch * CHL;
    #pragma unroll
    for (int q = 0; q < (CHL * DS) / 128; q++) {
        (&sB[0][0])[tid + q * 128] = g_Bt[tok0 * DS + tid + q * 128];
        (&sC[0][0])[tid + q * 128] = g_Ct[tok0 * DS + tid + q * 128];
    }
    const float* sp = g_S + ((size_t)(bb * NCH + ch) * DI + d) * DS;
    float a[DS], h[DS];
    #pragma unroll
    for (int s = 0; s < DS; s++) {
        a[s] = sigmoidf_(A[d * DS + s]);
        h[s] = sp[s];
    }
    float Dd = Dv[d];
    __syncthreads();
    for (int t = 0; t < CHL; t++) {
        int tok = tok0 + t;
        float x = __half2float(g_xch[(size_t)tok * DI + d]);
        float yv = Dd * x;
        #pragma unroll
        for (int s = 0; s < DS; s++) {
            h[s] = fmaf(a[s], h[s], sB[t][s] * x);
            yv = fmaf(h[s], sC[t][s], yv);
        }
        float gt = __half2float(g_projh[(size_t)tok * (2 * DI) + DI + d]);
        g_y[(size_t)tok * DI + d] = __float2half(yv * siluf_(gt));
    }
}

// ---------------- launch ----------------
extern "C" void kernel_launch(void* const* d_in, const int* in_sizes, int n_in,
                              void* d_out, int out_size) {
    const float* x      = (const float*)d_in[0];
    const float* ln_g   = (const float*)d_in[1];
    const float* ln_b   = (const float*)d_in[2];
    const float* W_in   = (const float*)d_in[3];
    const float* b_in   = (const float*)d_in[4];
    const float* conv_w = (const float*)d_in[5];
    const float* conv_b = (const float*)d_in[6];
    const float* A      = (const float*)d_in[7];
    const float* W_B    = (const float*)d_in[8];
    const float* b_B    = (const float*)d_in[9];
    const float* W_C    = (const float*)d_in[10];
    const float* b_C    = (const float*)d_in[11];
    const float* Dv     = (const float*)d_in[12];
    const float* W_out  = (const float*)d_in[13];
    const float* b_out  = (const float*)d_in[14];
    float* out = (float*)d_out;

    void *pxnh, *pprojh, *py, *pwih, *pwoh;
    cudaGetSymbolAddress(&pxnh,  g_xnh);
    cudaGetSymbolAddress(&pprojh, g_projh);
    cudaGetSymbolAddress(&py,    g_y);
    cudaGetSymbolAddress(&pwih,  g_WinH);
    cudaGetSymbolAddress(&pwoh,  g_WoutH);

    cudaFuncSetAttribute((const void*)gemm_f16<0, __half>,
                         cudaFuncAttributeMaxDynamicSharedMemorySize, GSM);
    cudaFuncSetAttribute((const void*)gemm_f16<1, float>,
                         cudaFuncAttributeMaxDynamicSharedMemorySize, GSM);
    cudaFuncSetAttribute((const void*)bc_mma_kernel,
                         cudaFuncAttributeMaxDynamicSharedMemorySize, CSM);

    // 1. fused prep (ln + both weight converts + wbc pack)
    prep_kernel<<<PREP_BLKS, 256>>>(x, ln_g, ln_b, W_in, W_out, W_B, W_C);

    // 2. proj = xn @ W_in + b_in    (M=2048, N=4096, K=1024), 128x128, 2 CTA/SM
    gemm_f16<0, __half><<<dim3((2 * DI) / 128, TOK / 128), 256, GSM>>>(
        (const __half*)pxnh, (const __half*)pwih, b_in, x /*unused*/,
        (__half*)pprojh, TOK, 2 * DI, DM);

    // 3.
    conv_silu_kernel<<<(TOK * DI) / 256, 256>>>(conv_w, conv_b);

    // 4. (profiled slot)
    bc_mma_kernel<<<dim3(TOK / 128, KSL), 256, CSM>>>();
    bc_reduce_kernel<<<(TOK * 32) / 256, 256>>>(b_B, b_C);

    scan1_kernel<<<dim3(DI / 128, NCH, B_), 128>>>(A);
    carry_kernel<<<(B_ * DI) / 256, 256>>>(A);
    scan2_kernel<<<dim3(DI / 128, NCH, B_), 128>>>(A, Dv);

    // 9. out = y @ W_out + b_out + x   (M=2048, N=1024, K=2048), 128x128, 2 CTA/SM
    gemm_f16<1, float><<<dim3(DM / 128, TOK / 128), 256, GSM>>>(
        (const __half*)py, (const __half*)pwoh, b_out, x, out, TOK, DM, DI);
}

// round 11
// speedup vs baseline: 3.4237x; 1.0209x over previous
#include <cuda_runtime.h>
#include <cuda_fp16.h>
#include <cstdint>

// ---------------- problem constants ----------------
#define B_   2
#define T_   1024
#define DM   1024      // d_model
#define DI   2048      // d_inner
#define DS   16        // d_state
#define TOK  (B_ * T_) // 2048 tokens
#define NCH  32        // scan chunks
#define CHL  32        // chunk length
#define KSL  8         // bc split-K slices

// ---------------- scratch (static device memory) ----------------
__device__ __half g_xnh  [TOK * DM];        // fp16 LN output (gemm1 A)
__device__ __half g_WinH [DM * 2 * DI];     // fp16 W_in
__device__ __half g_WoutH[DI * DM];         // fp16 W_out
__device__ __half g_WBC  [DI * 32];         // fp16 [W_B | W_C]
__device__ __half g_projh[TOK * 2 * DI];    // in_proj output (xp | gate), fp16
__device__ __half g_xch  [TOK * DI];        // conv+silu output fp16
__device__ float  g_Bt   [TOK * DS];
__device__ float  g_Ct   [TOK * DS];
__device__ float  g_E    [B_ * NCH * DI * DS];
__device__ float  g_S    [B_ * NCH * DI * DS];
__device__ __half g_y    [TOK * DI];        // gated SSM output fp16 (gemm2 A)
__device__ float  g_BCp  [KSL][TOK][32];
__device__ float  g_G2p  [2][TOK * DM];     // gemm2 split-K partials

__device__ __forceinline__ float sigmoidf_(float x) { return 1.0f / (1.0f + __expf(-x)); }
__device__ __forceinline__ float siluf_(float x)    { return x / (1.0f + __expf(-x)); }

__device__ __forceinline__ uint32_t smem_u32(const void* p) {
    uint32_t a;
    asm("{ .reg .u64 t; cvta.to.shared.u64 t, %1; cvt.u32.u64 %0, t; }"
        : "=r"(a) : "l"(p));
    return a;
}
__device__ __forceinline__ void cp16(uint32_t dst, const void* src) {
    asm volatile("cp.async.cg.shared.global [%0], [%1], 16;"
                 :: "r"(dst), "l"(src) : "memory");
}
__device__ __forceinline__ void ldsm4(uint32_t* r, uint32_t addr) {
    asm volatile("ldmatrix.sync.aligned.m8n8.x4.shared.b16 {%0,%1,%2,%3}, [%4];"
        : "=r"(r[0]), "=r"(r[1]), "=r"(r[2]), "=r"(r[3]) : "r"(addr));
}
__device__ __forceinline__ void ldsm4t(uint32_t* r, uint32_t addr) {
    asm volatile("ldmatrix.sync.aligned.m8n8.x4.trans.shared.b16 {%0,%1,%2,%3}, [%4];"
        : "=r"(r[0]), "=r"(r[1]), "=r"(r[2]), "=r"(r[3]) : "r"(addr));
}
__device__ __forceinline__ void mma_f16(float* c, const uint32_t* a, const uint32_t* b) {
    asm volatile(
        "mma.sync.aligned.m16n8k16.row.col.f32.f16.f16.f32 "
        "{%0,%1,%2,%3}, {%4,%5,%6,%7}, {%8,%9}, {%0,%1,%2,%3};"
        : "+f"(c[0]), "+f"(c[1]), "+f"(c[2]), "+f"(c[3])
        : "r"(a[0]), "r"(a[1]), "r"(a[2]), "r"(a[3]), "r"(b[0]), "r"(b[1]));
}

// ---------------- 1. fused prep: f2h(W_in) | f2h(W_out) | pack_wbc | LayerNorm ----------------
#define PREP_WIN_BLKS  ((DM * 2 * DI) / 1024)   // 4096
#define PREP_WOUT_BLKS ((DI * DM) / 1024)       // 2048
#define PREP_WBC_BLKS  ((DI * 32) / 256)        // 256
#define PREP_LN_BLKS   TOK                      // 2048
#define PREP_BLKS (PREP_WIN_BLKS + PREP_WOUT_BLKS + PREP_WBC_BLKS + PREP_LN_BLKS)

__global__ void prep_kernel(const float* __restrict__ x,
                            const float* __restrict__ ln_g,
                            const float* __restrict__ ln_b,
                            const float* __restrict__ W_in,
                            const float* __restrict__ W_out,
                            const float* __restrict__ WB,
                            const float* __restrict__ WC) {
    __shared__ float ss[8], sq[8];
    __shared__ float smu, srstd;
    int blk = blockIdx.x;
    int tid = threadIdx.x;

    if (blk < PREP_WIN_BLKS) {
        int i = blk * 256 + tid;
        float4 v = ((const float4*)W_in)[i];
        ((__half2*)g_WinH)[i * 2]     = __floats2half2_rn(v.x, v.y);
        ((__half2*)g_WinH)[i * 2 + 1] = __floats2half2_rn(v.z, v.w);
        return;
    }
    blk -= PREP_WIN_BLKS;
    if (blk < PREP_WOUT_BLKS) {
        int i = blk * 256 + tid;
        float4 v = ((const float4*)W_out)[i];
        ((__half2*)g_WoutH)[i * 2]     = __floats2half2_rn(v.x, v.y);
        ((__half2*)g_WoutH)[i * 2 + 1] = __floats2half2_rn(v.z, v.w);
        return;
    }
    blk -= PREP_WOUT_BLKS;
    if (blk < PREP_WBC_BLKS) {
        int i = blk * 256 + tid;
        int k = i >> 5, o = i & 31;
        float v = (o < 16) ? WB[k * DS + o] : WC[k * DS + (o - 16)];
        g_WBC[i] = __float2half(v);
        return;
    }
    blk -= PREP_WBC_BLKS;
    {
        int row = blk;
        const float4* xr = (const float4*)(x + (size_t)row * DM);
        float4 v = xr[tid];
        float s = v.x + v.y + v.z + v.w;
        float q = v.x * v.x + v.y * v.y + v.z * v.z + v.w * v.w;
        #pragma unroll
        for (int o = 16; o; o >>= 1) {
            s += __shfl_down_sync(0xFFFFFFFFu, s, o);
            q += __shfl_down_sync(0xFFFFFFFFu, q, o);
        }
        int w = tid >> 5, l = tid & 31;
        if (l == 0) { ss[w] = s; sq[w] = q; }
        __syncthreads();
        if (tid == 0) {
            float S = 0.f, Q = 0.f;
            #pragma unroll
            for (int i = 0; i < 8; i++) { S += ss[i]; Q += sq[i]; }
            float mu = S * (1.0f / DM);
            float var = Q * (1.0f / DM) - mu * mu;
            smu = mu; srstd = rsqrtf(var + 1e-5f);
        }
        __syncthreads();
        float mu = smu, rstd = srstd;
        float4 gv = ((const float4*)ln_g)[tid];
        float4 bv = ((const float4*)ln_b)[tid];
        __half2* orow = (__half2*)(g_xnh + (size_t)row * DM);
        orow[tid * 2]     = __floats2half2_rn((v.x - mu) * rstd * gv.x + bv.x,
                                              (v.y - mu) * rstd * gv.y + bv.y);
        orow[tid * 2 + 1] = __floats2half2_rn((v.z - mu) * rstd * gv.z + bv.z,
                                              (v.w - mu) * rstd * gv.w + bv.w);
    }
}

// ---------------- fp16 mma GEMM, 4-stage pipeline, 2 CTAs/SM ----------------
// MODE 0: C = A@B + bias (OutT fp16/fp32).  MODE 2: split-K2 partial, no bias, fp32.
// A: MxK fp16 row-major.  B: KxN fp16 row-major.  Block tile 128x128, K-step 32.
// Warp grid 2(m) x 4(n): warp tile 64 x 32.
#define GA_ST 80                    // A smem row stride bytes
#define GA_BYTES (128 * GA_ST)      // 10240
#define GB_ST 272                   // B smem row stride bytes
#define GB_BYTES (32 * GB_ST)       // 8704
#define GSTAGE (GA_BYTES + GB_BYTES)
#define GSM (4 * GSTAGE)            // 75776

template <int MODE, typename OutT>
__global__ __launch_bounds__(256, 2) void gemm_f16(
    const __half* __restrict__ Amat, const __half* __restrict__ Bmat,
    const float* __restrict__ bias,
    OutT* __restrict__ Cmat, int M, int N, int K)
{
    extern __shared__ char sm[];
    uint32_t sb = smem_u32(sm);
    int tid = threadIdx.x;
    int wid = tid >> 5, lane = tid & 31;
    int wm = wid >> 2, wn = wid & 3;
    int gid = lane >> 2, tig = lane & 3;
    int mBase = blockIdx.y * 128, nBase = blockIdx.x * 128;
    int kOff = (MODE == 2) ? blockIdx.z * (K / 2) : 0;
    const int S = (MODE == 2) ? (K / 2) / 32 : K / 32;
    OutT* Cout = (MODE == 2) ? Cmat + (size_t)blockIdx.z * M * N : Cmat;

    float acc[4][4][4];
    #pragma unroll
    for (int i = 0; i < 4; i++)
        #pragma unroll
        for (int j = 0; j < 4; j++)
            #pragma unroll
            for (int c = 0; c < 4; c++) acc[i][j][c] = 0.f;

    auto stage_load = [&](int buf, int k0) {
        uint32_t ab = sb + buf * GSTAGE;
        uint32_t bb = ab + GA_BYTES;
        #pragma unroll
        for (int q = 0; q < 2; q++) {                 // A: 128 rows x 4 chunks
            int lin = tid + q * 256;
            int row = lin >> 2, ch = lin & 3;
            cp16(ab + row * GA_ST + ch * 16,
                 Amat + (size_t)(mBase + row) * K + k0 + ch * 8);
        }
        #pragma unroll
        for (int q = 0; q < 2; q++) {                 // B: 32 rows x 16 chunks
            int lin = tid + q * 256;
            int row = lin >> 4, ch = lin & 15;
            cp16(bb + row * GB_ST + ch * 16,
                 Bmat + (size_t)(k0 + row) * N + nBase + ch * 8);
        }
        asm volatile("cp.async.commit_group;" ::: "memory");
    };

    stage_load(0, kOff);
    stage_load(1, kOff + 32);
    stage_load(2, kOff + 64);
    for (int s = 0; s < S; s++) {
        asm volatile("cp.async.wait_group 2;" ::: "memory");
        __syncthreads();
        if (s + 3 < S) stage_load((s + 3) & 3, kOff + (s + 3) * 32);
        else           asm volatile("cp.async.commit_group;" ::: "memory");  // empty group keeps accounting uniform

        uint32_t ab = sb + (s & 3) * GSTAGE;
        uint32_t bb = ab + GA_BYTES;
        #pragma unroll
        for (int k16 = 0; k16 < 2; k16++) {
            uint32_t af[4][4], bf[2][4];
            #pragma unroll
            for (int mt = 0; mt < 4; mt++) {
                uint32_t addr = ab + (wm * 64 + mt * 16 + (lane & 15)) * GA_ST
                              + k16 * 32 + ((lane >> 4) << 4);
                ldsm4(af[mt], addr);
            }
            #pragma unroll
            for (int bt = 0; bt < 2; bt++) {
                uint32_t addr = bb + (k16 * 16 + (lane & 15)) * GB_ST
                              + (wn * 32 + bt * 16 + ((lane >> 4) << 3)) * 2;
                ldsm4t(bf[bt], addr);
            }
            #pragma unroll
            for (int mt = 0; mt < 4; mt++)
                #pragma unroll
                for (int nt = 0; nt < 4; nt++)
                    mma_f16(acc[mt][nt], af[mt], &bf[nt >> 1][(nt & 1) * 2]);
        }
        __syncthreads();
    }

    #pragma unroll
    for (int mt = 0; mt < 4; mt++) {
        int r0 = mBase + wm * 64 + mt * 16 + gid;
        #pragma unroll
        for (int nt = 0; nt < 4; nt++) {
            int cN = nBase + wn * 32 + nt * 8 + tig * 2;
            float o0x = acc[mt][nt][0], o0y = acc[mt][nt][1];
            float o1x = acc[mt][nt][2], o1y = acc[mt][nt][3];
            if (MODE == 0) {
                float2 bv = *(const float2*)(bias + cN);
                o0x += bv.x; o0y += bv.y;
                o1x += bv.x; o1y += bv.y;
            }
            if (sizeof(OutT) == 2) {
                *(__half2*)((__half*)Cout + (size_t)r0 * N + cN)       = __floats2half2_rn(o0x, o0y);
                *(__half2*)((__half*)Cout + (size_t)(r0 + 8) * N + cN) = __floats2half2_rn(o1x, o1y);
            } else {
                *(float2*)((float*)Cout + (size_t)r0 * N + cN)       = make_float2(o0x, o0y);
                *(float2*)((float*)Cout + (size_t)(r0 + 8) * N + cN) = make_float2(o1x, o1y);
            }
        }
    }
}

// ---------------- gemm2 split-K reduce: out = p0 + p1 + bias + x ----------------
__global__ void g2_reduce_kernel(const float* __restrict__ bias,
                                 const float* __restrict__ x,
                                 float* __restrict__ out) {
    int i = blockIdx.x * 256 + threadIdx.x;       // over TOK*DM/4 float4s
    float4 p0 = ((const float4*)g_G2p[0])[i];
    float4 p1 = ((const float4*)g_G2p[1])[i];
    float4 bv = ((const float4*)bias)[i & (DM / 4 - 1)];
    float4 xv = ((const float4*)x)[i];
    float4 o;
    o.x = p0.x + p1.x + bv.x + xv.x;
    o.y = p0.y + p1.y + bv.y + xv.y;
    o.z = p0.z + p1.z + bv.z + xv.z;
    o.w = p0.w + p1.w + bv.w + xv.w;
    ((float4*)out)[i] = o;
}

// ---------------- 3. depthwise causal conv1d + silu (fp16 in/out) ----------------
__global__ void conv_silu_kernel(const float* __restrict__ cw,
                                 const float* __restrict__ cb) {
    int i = blockIdx.x * 256 + threadIdx.x;
    int d   = i & (DI - 1);
    int tok = i >> 11;
    int t   = tok & (T_ - 1);
    float4 w = *(const float4*)(cw + d * 4);
    const __half* base = g_projh + (size_t)tok * (2 * DI) + d;
    float acc = cb[d];
    if (t >= 3) acc = fmaf(w.x, __half2float(base[-3 * 2 * DI]), acc);
    if (t >= 2) acc = fmaf(w.y, __half2float(base[-2 * 2 * DI]), acc);
    if (t >= 1) acc = fmaf(w.z, __half2float(base[-1 * 2 * DI]), acc);
    acc = fmaf(w.w, __half2float(base[0]), acc);
    g_xch[i] = __float2half(siluf_(acc));
}

// ---------------- 4. B_t / C_t: fp16 mma split-K GEMM (M=TOK, N=32, K=DI) ----------------
#define CA_BYTES (128 * 80)
#define CB_BYTES (32 * 80)
#define CSTAGE (CA_BYTES + CB_BYTES)
#define CSM (3 * CSTAGE)

__global__ __launch_bounds__(256) void bc_mma_kernel() {
    extern __shared__ char sm[];
    uint32_t sb = smem_u32(sm);
    int tid = threadIdx.x;
    int wid = tid >> 5, lane = tid & 31;
    int wm = wid >> 1, wn = wid & 1;
    int gid = lane >> 2, tig = lane & 3;
    int tok0 = blockIdx.x * 128;
    int kBase = blockIdx.y * (DI / KSL);
    const __half* X = g_xch;
    const __half* W = g_WBC;

    float acc[2][2][4];
    #pragma unroll
    for (int i = 0; i < 2; i++)
        #pragma unroll
        for (int j = 0; j < 2; j++)
            #pragma unroll
            for (int c = 0; c < 4; c++) acc[i][j][c] = 0.f;

    auto stage_load = [&](int buf, int k0) {
        uint32_t ab = sb + buf * CSTAGE;
        uint32_t bb = ab + CA_BYTES;
        #pragma unroll
        for (int q = 0; q < 2; q++) {
            int lin = tid + q * 256;
            int row = lin >> 2, ch = lin & 3;
            cp16(ab + row * 80 + ch * 16,
                 X + (size_t)(tok0 + row) * DI + kBase + k0 + ch * 8);
        }
        if (tid < 128) {
            int row = tid >> 2, ch = tid & 3;
            cp16(bb + row * 80 + ch * 16,
                 W + (size_t)(kBase + k0 + row) * 32 + ch * 8);
        }
        asm volatile("cp.async.commit_group;" ::: "memory");
    };

    const int S = (DI / KSL) / 32;
    stage_load(0, 0);
    stage_load(1, 32);
    for (int s = 0; s < S; s++) {
        asm volatile("cp.async.wait_group 1;" ::: "memory");
        __syncthreads();
        if (s + 2 < S) stage_load((s + 2) % 3, (s + 2) * 32);

        uint32_t ab = sb + (s % 3) * CSTAGE;
        uint32_t bb = ab + CA_BYTES;
        #pragma unroll
        for (int k16 = 0; k16 < 2; k16++) {
            uint32_t af[2][4], bf[4];
            #pragma unroll
            for (int mt = 0; mt < 2; mt++) {
                uint32_t addr = ab + (wm * 32 + mt * 16 + (lane & 15)) * 80
                              + k16 * 32 + ((lane >> 4) << 4);
                ldsm4(af[mt], addr);
            }
            {
                uint32_t addr = bb + (k16 * 16 + (lane & 15)) * 80
                              + (wn * 16 + ((lane >> 4) << 3)) * 2;
                ldsm4t(bf, addr);
            }
            #pragma unroll
            for (int mt = 0; mt < 2; mt++)
                #pragma unroll
                for (int nt = 0; nt < 2; nt++)
                    mma_f16(acc[mt][nt], af[mt], &bf[nt * 2]);
        }
        __syncthreads();
    }

    #pragma unroll
    for (int mt = 0; mt < 2; mt++) {
        int r0 = tok0 + wm * 32 + mt * 16 + gid;
        #pragma unroll
        for (int nt = 0; nt < 2; nt++) {
            int o = wn * 16 + nt * 8 + tig * 2;
            *(float2*)&g_BCp[blockIdx.y][r0][o]     = make_float2(acc[mt][nt][0], acc[mt][nt][1]);
            *(float2*)&g_BCp[blockIdx.y][r0 + 8][o] = make_float2(acc[mt][nt][2], acc[mt][nt][3]);
        }
    }
}

__global__ void bc_reduce_kernel(const float* __restrict__ bB,
                                 const float* __restrict__ bC) {
    int idx = blockIdx.x * 256 + threadIdx.x;
    int o = idx & 31, tok = idx >> 5;
    float s = 0.f;
    #pragma unroll
    for (int p = 0; p < KSL; p++) s += g_BCp[p][tok][o];
    if (o < 16) g_Bt[tok * DS + o]        = s + bB[o];
    else        g_Ct[tok * DS + (o - 16)] = s + bC[o - 16];
}

// ---------------- 5. scan pass 1 ----------------
__global__ void scan1_kernel(const float* __restrict__ A) {
    __shared__ float sB[CHL][DS];
    int tid = threadIdx.x;
    int d  = blockIdx.x * 128 + tid;
    int ch = blockIdx.y, bb = blockIdx.z;
    int tok0 = bb * T_ + ch * CHL;
    float* sBf = &sB[0][0];
    #pragma unroll
    for (int q = 0; q < (CHL * DS) / 128; q++)
        sBf[tid + q * 128] = g_Bt[tok0 * DS + tid + q * 128];
    float a[DS], h[DS];
    #pragma unroll
    for (int s = 0; s < DS; s++) {
        a[s] = sigmoidf_(A[d * DS + s]);
        h[s] = 0.f;
    }
    __syncthreads();
    for (int t = 0; t < CHL; t++) {
        float x = __half2float(g_xch[(size_t)(tok0 + t) * DI + d]);
        #pragma unroll
        for (int s = 0; s < DS; s++)
            h[s] = fmaf(a[s], h[s], sB[t][s] * x);
    }
    float* ep = g_E + ((size_t)(bb * NCH + ch) * DI + d) * DS;
    #pragma unroll
    for (int s = 0; s < DS; s++) ep[s] = h[s];
}

// ---------------- 6. serial carry across chunks ----------------
__global__ void carry_kernel(const float* __restrict__ A) {
    int idx = blockIdx.x * 256 + threadIdx.x;
    int d = idx & (DI - 1), bb = idx >> 11;
    float aL[DS], st[DS];
    #pragma unroll
    for (int s = 0; s < DS; s++) {
        float a = sigmoidf_(A[d * DS + s]);
        #pragma unroll
        for (int r = 0; r < 5; r++) a *= a;   // a^32 (CHL=32)
        aL[s] = a;
        st[s] = 0.f;
    }
    for (int c = 0; c < NCH; c++) {
        float* sp = g_S + ((size_t)(bb * NCH + c) * DI + d) * DS;
        const float* ep = g_E + ((size_t)(bb * NCH + c) * DI + d) * DS;
        #pragma unroll
        for (int s = 0; s < DS; s++) sp[s] = st[s];
        #pragma unroll
        for (int s = 0; s < DS; s++) st[s] = fmaf(aL[s], st[s], ep[s]);
    }
}

// ---------------- 7. scan pass 2 + gate epilogue ----------------
__global__ void scan2_kernel(const float* __restrict__ A,
                             const float* __restrict__ Dv) {
    __shared__ float sB[CHL][DS], sC[CHL][DS];
    int tid = threadIdx.x;
    int d  = blockIdx.x * 128 + tid;
    int ch = blockIdx.y, bb = blockIdx.z;
    int tok0 = bb * T_ + ch * CHL;
    #pragma unroll
    for (int q = 0; q < (CHL * DS) / 128; q++) {
        (&sB[0][0])[tid + q * 128] = g_Bt[tok0 * DS + tid + q * 128];
        (&sC[0][0])[tid + q * 128] = g_Ct[tok0 * DS + tid + q * 128];
    }
    const float* sp = g_S + ((size_t)(bb * NCH + ch) * DI + d) * DS;
    float a[DS], h[DS];
    #pragma unroll
    for (int s = 0; s < DS; s++) {
        a[s] = sigmoidf_(A[d * DS + s]);
        h[s] = sp[s];
    }
    float Dd = Dv[d];
    __syncthreads();
    for (int t = 0; t < CHL; t++) {
        int tok = tok0 + t;
        float x = __half2float(g_xch[(size_t)tok * DI + d]);
        float yv = Dd * x;
        #pragma unroll
        for (int s = 0; s < DS; s++) {
            h[s] = fmaf(a[s], h[s], sB[t][s] * x);
            yv = fmaf(h[s], sC[t][s], yv);
        }
        float gt = __half2float(g_projh[(size_t)tok * (2 * DI) + DI + d]);
        g_y[(size_t)tok * DI + d] = __float2half(yv * siluf_(gt));
    }
}

// ---------------- launch ----------------
extern "C" void kernel_launch(void* const* d_in, const int* in_sizes, int n_in,
                              void* d_out, int out_size) {
    const float* x      = (const float*)d_in[0];
    const float* ln_g   = (const float*)d_in[1];
    const float* ln_b   = (const float*)d_in[2];
    const float* W_in   = (const float*)d_in[3];
    const float* b_in   = (const float*)d_in[4];
    const float* conv_w = (const float*)d_in[5];
    const float* conv_b = (const float*)d_in[6];
    const float* A      = (const float*)d_in[7];
    const float* W_B    = (const float*)d_in[8];
    const float* b_B    = (const float*)d_in[9];
    const float* W_C    = (const float*)d_in[10];
    const float* b_C    = (const float*)d_in[11];
    const float* Dv     = (const float*)d_in[12];
    const float* W_out  = (const float*)d_in[13];
    const float* b_out  = (const float*)d_in[14];
    float* out = (float*)d_out;

    void *pxnh, *pprojh, *py, *pwih, *pwoh, *pg2p;
    cudaGetSymbolAddress(&pxnh,  g_xnh);
    cudaGetSymbolAddress(&pprojh, g_projh);
    cudaGetSymbolAddress(&py,    g_y);
    cudaGetSymbolAddress(&pwih,  g_WinH);
    cudaGetSymbolAddress(&pwoh,  g_WoutH);
    cudaGetSymbolAddress(&pg2p,  g_G2p);

    cudaFuncSetAttribute((const void*)gemm_f16<0, __half>,
                         cudaFuncAttributeMaxDynamicSharedMemorySize, GSM);
    cudaFuncSetAttribute((const void*)gemm_f16<2, float>,
                         cudaFuncAttributeMaxDynamicSharedMemorySize, GSM);
    cudaFuncSetAttribute((const void*)bc_mma_kernel,
                         cudaFuncAttributeMaxDynamicSharedMemorySize, CSM);

    // 1. fused prep (ln + both weight converts + wbc pack)
    prep_kernel<<<PREP_BLKS, 256>>>(x, ln_g, ln_b, W_in, W_out, W_B, W_C);

    // 2. proj = xn @ W_in + b_in   (M=2048, N=4096, K=1024), 4-stage, 2 CTA/SM
    gemm_f16<0, __half><<<dim3((2 * DI) / 128, TOK / 128), 256, GSM>>>(
        (const __half*)pxnh, (const __half*)pwih, b_in,
        (__half*)pprojh, TOK, 2 * DI, DM);

    // 3.
    conv_silu_kernel<<<(TOK * DI) / 256, 256>>>(conv_w, conv_b);

    // 4.
    bc_mma_kernel<<<dim3(TOK / 128, KSL), 256, CSM>>>();
    bc_reduce_kernel<<<(TOK * 32) / 256, 256>>>(b_B, b_C);

    scan1_kernel<<<dim3(DI / 128, NCH, B_), 128>>>(A);
    carry_kernel<<<(B_ * DI) / 256, 256>>>(A);
    scan2_kernel<<<dim3(DI / 128, NCH, B_), 128>>>(A, Dv);

    // 9. gemm2 split-K2 partials (M=2048, N=1024, K=2048; 256 CTAs) + reduce
    gemm_f16<2, float><<<dim3(DM / 128, TOK / 128, 2), 256, GSM>>>(
        (const __half*)py, (const __half*)pwoh, b_out,
        (float*)pg2p, TOK, DM, DI);
    g2_reduce_kernel<<<(TOK * DM) / 1024, 256>>>(b_out, x, out);
}